// round 1
// baseline (speedup 1.0000x reference)
#include <cuda_runtime.h>

// ---------------------------------------------------------------------------
// Problem constants
// ---------------------------------------------------------------------------
#define NTOK    294         // tokens per window = 6*7*7
#define NWIN    288         // windows = 2*12*12
#define D_MODEL 256
#define HEADS   8
#define DH      32
#define M_ROWS  (NWIN * NTOK)   // 84672
#define QKV_N   768

// GEMM tiling
#define BM 64
#define BN 128
#define BK 16
#define AS_STRIDE 68        // padded (multiple of 4 floats for aligned float4)

// ---------------------------------------------------------------------------
// Scratch (__device__ globals: allocation-free rule)
// ---------------------------------------------------------------------------
__device__ float g_q  [(size_t)NWIN * HEADS * NTOK * DH];
__device__ float g_k  [(size_t)NWIN * HEADS * NTOK * DH];
__device__ float g_v  [(size_t)NWIN * HEADS * NTOK * DH];
__device__ float g_ctx[(size_t)M_ROWS * D_MODEL];

// Row r of the logical (B, n, d) tensor maps to a contiguous 256-float segment
// of x (and of the final output): same permutation both directions.
__device__ __forceinline__ int x_offset(int r) {
    int w  = r / NTOK;  int t   = r - w * NTOK;
    int bb = w / 144;   int rem = w - bb * 144;
    int gx = rem / 12;  int gy  = rem - gx * 12;
    int l  = t / 49;    int t2  = t - l * 49;
    int w1 = t2 / 7;    int w2  = t2 - w1 * 7;
    return (((((bb * 6 + l) * 12 + gx) * 12 + gy) * 7 + w1) * 7 + w2) * D_MODEL;
}

// ---------------------------------------------------------------------------
// Kernel 1: fused QKV projection.  A = gathered x rows (84672 x 256),
// B = [Wq | Wkv] (256 x 768).  Epilogue adds bias, folds softmax scale into q,
// and stores q/k/v in (win, head, tok, dh) layout.
// ---------------------------------------------------------------------------
__global__ __launch_bounds__(256) void qkv_gemm(
    const float* __restrict__ x,
    const float* __restrict__ Wq,  const float* __restrict__ bq,
    const float* __restrict__ Wkv, const float* __restrict__ bkv)
{
    __shared__ float As[BK * AS_STRIDE];
    __shared__ float Bs[BK * BN];
    __shared__ int   rowbase[BM];

    const int tid = threadIdx.x;
    const int r0  = blockIdx.x * BM;
    const int c0  = blockIdx.y * BN;

    const float* Bsrc; int ldb, coff;
    if (c0 < D_MODEL) { Bsrc = Wq;  ldb = D_MODEL;     coff = c0; }
    else              { Bsrc = Wkv; ldb = 2 * D_MODEL; coff = c0 - D_MODEL; }

    if (tid < BM) rowbase[tid] = x_offset(r0 + tid);
    __syncthreads();

    const int tx = tid & 15;    // col group (x8)
    const int ty = tid >> 4;    // row group (x4)

    const int la = tid >> 2;    // A loader: row 0..63
    const int kq = tid & 3;     // A loader: float4 within k-chunk
    const int bk = tid >> 4;    // B loader: k row 0..15
    const int bc = (tid & 15) * 8;

    const int   arow = rowbase[la];
    const float* bp  = Bsrc + coff + bc;

    float acc[4][8];
#pragma unroll
    for (int i = 0; i < 4; i++)
#pragma unroll
        for (int j = 0; j < 8; j++) acc[i][j] = 0.f;

    for (int k0 = 0; k0 < D_MODEL; k0 += BK) {
        float4 a4 = *(const float4*)(x + arow + k0 + kq * 4);
        float4 b0 = *(const float4*)(bp + (size_t)(k0 + bk) * ldb);
        float4 b1 = *(const float4*)(bp + (size_t)(k0 + bk) * ldb + 4);
        __syncthreads();
        As[(kq * 4 + 0) * AS_STRIDE + la] = a4.x;
        As[(kq * 4 + 1) * AS_STRIDE + la] = a4.y;
        As[(kq * 4 + 2) * AS_STRIDE + la] = a4.z;
        As[(kq * 4 + 3) * AS_STRIDE + la] = a4.w;
        *(float4*)(Bs + bk * BN + bc)     = b0;
        *(float4*)(Bs + bk * BN + bc + 4) = b1;
        __syncthreads();
#pragma unroll
        for (int k = 0; k < BK; k++) {
            float4 av  = *(const float4*)(As + k * AS_STRIDE + ty * 4);
            float4 bv0 = *(const float4*)(Bs + k * BN + tx * 8);
            float4 bv1 = *(const float4*)(Bs + k * BN + tx * 8 + 4);
            float a[4] = {av.x, av.y, av.z, av.w};
            float b[8] = {bv0.x, bv0.y, bv0.z, bv0.w, bv1.x, bv1.y, bv1.z, bv1.w};
#pragma unroll
            for (int i = 0; i < 4; i++)
#pragma unroll
                for (int j = 0; j < 8; j++) acc[i][j] += a[i] * b[j];
        }
    }

    const float scale = 0.17677669529663687f;  // 32^-0.5
#pragma unroll
    for (int i = 0; i < 4; i++) {
        int r = r0 + ty * 4 + i;
        int w = r / NTOK;  int t = r - w * NTOK;
#pragma unroll
        for (int j = 0; j < 8; j++) {
            int   nc = c0 + tx * 8 + j;
            float va = acc[i][j];
            if (nc < D_MODEL) {
                int h = nc >> 5, c = nc & 31;
                g_q[(((size_t)w * HEADS + h) * NTOK + t) * DH + c] = (va + bq[nc]) * scale;
            } else {
                int kc = nc - D_MODEL;
                float val = va + bkv[kc];
                if (kc < D_MODEL) {
                    int h = kc >> 5, c = kc & 31;
                    g_k[(((size_t)w * HEADS + h) * NTOK + t) * DH + c] = val;
                } else {
                    int vc = kc - D_MODEL;
                    int h = vc >> 5, c = vc & 31;
                    g_v[(((size_t)w * HEADS + h) * NTOK + t) * DH + c] = val;
                }
            }
        }
    }
}

// ---------------------------------------------------------------------------
// Kernel 2: fused window attention, one CTA per (window, head).
// K/V staged in dynamic smem; one thread per query row; online softmax.
// Relative-position bias: idx = C_i - base_j (separable), bias_table L1-hot.
// ---------------------------------------------------------------------------
__global__ __launch_bounds__(320) void attn_kernel(const float* __restrict__ bias_table)
{
    extern __shared__ float sm[];
    float* Ks    = sm;                    // 294*32
    float* Vs    = sm + NTOK * DH;        // 294*32
    int*   baseJ = (int*)(Vs + NTOK * DH);

    const int wh = blockIdx.x;            // w*8 + h
    const int w  = wh >> 3;
    const int h  = wh & 7;
    const int tid = threadIdx.x;

    const float* kp = g_k + (size_t)wh * NTOK * DH;
    const float* vp = g_v + (size_t)wh * NTOK * DH;
    for (int idx = tid; idx < NTOK * DH / 4; idx += blockDim.x) {
        ((float4*)Ks)[idx] = ((const float4*)kp)[idx];
        ((float4*)Vs)[idx] = ((const float4*)vp)[idx];
    }
    for (int j = tid; j < NTOK; j += blockDim.x) {
        int l = j / 49, t2 = j - l * 49, a = t2 / 7, bcol = t2 - a * 7;
        baseJ[j] = l * 169 + a * 13 + bcol;
    }
    __syncthreads();

    const int i = tid;
    if (i < NTOK) {
        float q[DH];
        const float* qp = g_q + ((size_t)wh * NTOK + i) * DH;
#pragma unroll
        for (int cc = 0; cc < 8; cc++) {
            float4 v4 = ((const float4*)qp)[cc];
            q[cc * 4 + 0] = v4.x; q[cc * 4 + 1] = v4.y;
            q[cc * 4 + 2] = v4.z; q[cc * 4 + 3] = v4.w;
        }
        int li = i / 49, ti2 = i - li * 49, ai = ti2 / 7, bi = ti2 - ai * 7;
        const int Ci = (li + 5) * 169 + (ai + 6) * 13 + (bi + 6);

        float m = -INFINITY, ssum = 0.f;
        float o[DH];
#pragma unroll
        for (int c = 0; c < DH; c++) o[c] = 0.f;

        for (int j = 0; j < NTOK; j++) {
            const float4* k4 = (const float4*)(Ks + j * DH);
            float s = 0.f;
#pragma unroll
            for (int cc = 0; cc < 8; cc++) {
                float4 kv = k4[cc];
                s += q[cc * 4 + 0] * kv.x + q[cc * 4 + 1] * kv.y
                   + q[cc * 4 + 2] * kv.z + q[cc * 4 + 3] * kv.w;
            }
            s += __ldg(bias_table + (size_t)(Ci - baseJ[j]) * HEADS + h);

            if (s > m) {
                float corr = __expf(m - s);
                m = s;
                ssum *= corr;
#pragma unroll
                for (int c = 0; c < DH; c++) o[c] *= corr;
            }
            float p = __expf(s - m);
            ssum += p;
            const float4* v4p = (const float4*)(Vs + j * DH);
#pragma unroll
            for (int cc = 0; cc < 8; cc++) {
                float4 vv = v4p[cc];
                o[cc * 4 + 0] += p * vv.x; o[cc * 4 + 1] += p * vv.y;
                o[cc * 4 + 2] += p * vv.z; o[cc * 4 + 3] += p * vv.w;
            }
        }
        float inv = 1.0f / ssum;
        float* op = g_ctx + ((size_t)w * NTOK + i) * D_MODEL + h * DH;
#pragma unroll
        for (int c = 0; c < DH; c++) op[c] = o[c] * inv;
    }
}

// ---------------------------------------------------------------------------
// Kernel 3: output projection  g_ctx (84672 x 256) @ Wout (256 x 256),
// scatter epilogue back into the (b,l,gx,gy,w1,w2,d) output layout.
// ---------------------------------------------------------------------------
__global__ __launch_bounds__(256) void out_gemm(
    const float* __restrict__ Wout, float* __restrict__ out)
{
    __shared__ float As[BK * AS_STRIDE];
    __shared__ float Bs[BK * BN];
    __shared__ int   rowbase[BM];

    const int tid = threadIdx.x;
    const int r0  = blockIdx.x * BM;
    const int c0  = blockIdx.y * BN;

    if (tid < BM) rowbase[tid] = x_offset(r0 + tid);
    __syncthreads();

    const int tx = tid & 15;
    const int ty = tid >> 4;
    const int la = tid >> 2;
    const int kq = tid & 3;
    const int bk = tid >> 4;
    const int bc = (tid & 15) * 8;

    const float* ap = g_ctx + (size_t)(r0 + la) * D_MODEL + kq * 4;
    const float* bp = Wout + c0 + bc;

    float acc[4][8];
#pragma unroll
    for (int i = 0; i < 4; i++)
#pragma unroll
        for (int j = 0; j < 8; j++) acc[i][j] = 0.f;

    for (int k0 = 0; k0 < D_MODEL; k0 += BK) {
        float4 a4 = *(const float4*)(ap + k0);
        float4 b0 = *(const float4*)(bp + (size_t)(k0 + bk) * D_MODEL);
        float4 b1 = *(const float4*)(bp + (size_t)(k0 + bk) * D_MODEL + 4);
        __syncthreads();
        As[(kq * 4 + 0) * AS_STRIDE + la] = a4.x;
        As[(kq * 4 + 1) * AS_STRIDE + la] = a4.y;
        As[(kq * 4 + 2) * AS_STRIDE + la] = a4.z;
        As[(kq * 4 + 3) * AS_STRIDE + la] = a4.w;
        *(float4*)(Bs + bk * BN + bc)     = b0;
        *(float4*)(Bs + bk * BN + bc + 4) = b1;
        __syncthreads();
#pragma unroll
        for (int k = 0; k < BK; k++) {
            float4 av  = *(const float4*)(As + k * AS_STRIDE + ty * 4);
            float4 bv0 = *(const float4*)(Bs + k * BN + tx * 8);
            float4 bv1 = *(const float4*)(Bs + k * BN + tx * 8 + 4);
            float a[4] = {av.x, av.y, av.z, av.w};
            float b[8] = {bv0.x, bv0.y, bv0.z, bv0.w, bv1.x, bv1.y, bv1.z, bv1.w};
#pragma unroll
            for (int i = 0; i < 4; i++)
#pragma unroll
                for (int j = 0; j < 8; j++) acc[i][j] += a[i] * b[j];
        }
    }

#pragma unroll
    for (int i = 0; i < 4; i++) {
        int xb = rowbase[ty * 4 + i];
#pragma unroll
        for (int j = 0; j < 8; j++) {
            out[xb + c0 + tx * 8 + j] = acc[i][j];
        }
    }
}

// ---------------------------------------------------------------------------
// Launch
// ---------------------------------------------------------------------------
extern "C" void kernel_launch(void* const* d_in, const int* in_sizes, int n_in,
                              void* d_out, int out_size)
{
    const float* x    = (const float*)d_in[0];
    const float* Wq   = (const float*)d_in[1];
    const float* bq   = (const float*)d_in[2];
    const float* Wkv  = (const float*)d_in[3];
    const float* bkv  = (const float*)d_in[4];
    const float* Wout = (const float*)d_in[5];
    const float* bias = (const float*)d_in[6];
    float* out = (float*)d_out;

    const int attn_smem = (NTOK * DH * 2) * 4 + NTOK * 4;  // 76440 B
    cudaFuncSetAttribute(attn_kernel,
                         cudaFuncAttributeMaxDynamicSharedMemorySize, attn_smem);

    dim3 g1(M_ROWS / BM, QKV_N / BN);       // (1323, 6)
    qkv_gemm<<<g1, 256>>>(x, Wq, bq, Wkv, bkv);

    attn_kernel<<<NWIN * HEADS, 320, attn_smem>>>(bias);

    dim3 g2(M_ROWS / BM, D_MODEL / BN);     // (1323, 2)
    out_gemm<<<g2, 256>>>(Wout, out);
}

// round 4
// speedup vs baseline: 1.8315x; 1.8315x over previous
#include <cuda_runtime.h>

// ---------------------------------------------------------------------------
// Problem constants
// ---------------------------------------------------------------------------
#define NTOK    294
#define NPAD    304            // padded tokens (19 * 16)
#define NT16    19             // m16 tiles over padded tokens
#define NWIN    288
#define D_MODEL 256
#define HEADS   8
#define DH      32
#define M_ROWS  (NWIN * NTOK)  // 84672
#define QKV_N   768

// smem strides (floats) chosen for conflict-free tf32 fragment loads
#define QS  36   // Q/K rows (32 cols):  stride%32==4  -> banks 4g+t bijective
#define VS  40   // V rows   (32 cols):  stride%32==8  -> banks 8t+g bijective
#define SS  308  // S rows   (304 cols): stride%32==20 -> banks 20g+t bijective
#define BSS 72   // GEMM B tile rows (64 cols): stride%32==8 -> banks 8t+g bijective

// ---------------------------------------------------------------------------
// Scratch
// ---------------------------------------------------------------------------
__device__ float g_q  [(size_t)NWIN * HEADS * NTOK * DH];
__device__ float g_k  [(size_t)NWIN * HEADS * NTOK * DH];
__device__ float g_v  [(size_t)NWIN * HEADS * NTOK * DH];
__device__ float g_ctx[(size_t)M_ROWS * D_MODEL];

__device__ __forceinline__ int x_offset(int r) {
    int w  = r / NTOK;  int t   = r - w * NTOK;
    int bb = w / 144;   int rem = w - bb * 144;
    int gx = rem / 12;  int gy  = rem - gx * 12;
    int l  = t / 49;    int t2  = t - l * 49;
    int w1 = t2 / 7;    int w2  = t2 - w1 * 7;
    return (((((bb * 6 + l) * 12 + gx) * 12 + gy) * 7 + w1) * 7 + w2) * D_MODEL;
}

__device__ __forceinline__ unsigned f2tf(float f) {
    unsigned u;
    asm("cvt.rna.tf32.f32 %0, %1;" : "=r"(u) : "f"(f));
    return u;
}
__device__ __forceinline__ unsigned fbits(float f) { return __float_as_uint(f); }

__device__ __forceinline__ void mma_tf32(float c[4], const unsigned a[4], const unsigned b[2]) {
    asm volatile(
        "mma.sync.aligned.m16n8k8.row.col.f32.tf32.tf32.f32 "
        "{%0,%1,%2,%3}, {%4,%5,%6,%7}, {%8,%9}, {%0,%1,%2,%3};"
        : "+f"(c[0]), "+f"(c[1]), "+f"(c[2]), "+f"(c[3])
        : "r"(a[0]), "r"(a[1]), "r"(a[2]), "r"(a[3]), "r"(b[0]), "r"(b[1]));
}

// ===========================================================================
// Kernel 1: QKV projection (tf32 tensor cores)
// C = gather(x)[84672 x 256] @ [Wq|Wkv][256 x 768], epilogue scatter.
// CTA tile 64x64, 4 warps of 32x32, BK=32.
// ===========================================================================
__global__ __launch_bounds__(128) void qkv_gemm_tc(
    const float* __restrict__ x,
    const float* __restrict__ Wq,  const float* __restrict__ bq,
    const float* __restrict__ Wkv, const float* __restrict__ bkv)
{
    __shared__ float As[64 * QS];    // [m][k] stride 36
    __shared__ float Bs[32 * BSS];   // [k][n] stride 72 (64 cols)
    __shared__ int   rowbase[64];

    const int tid  = threadIdx.x;
    const int lane = tid & 31, wid = tid >> 5;
    const int wm = wid & 1, wn = wid >> 1;
    const int g = lane >> 2, t = lane & 3;
    const int r0 = blockIdx.x * 64;
    const int c0 = blockIdx.y * 64;

    const float* Bsrc; int ldb, coff;
    if (c0 < D_MODEL) { Bsrc = Wq;  ldb = D_MODEL;     coff = c0; }
    else              { Bsrc = Wkv; ldb = 2 * D_MODEL; coff = c0 - D_MODEL; }

    if (tid < 64) rowbase[tid] = x_offset(r0 + tid);
    __syncthreads();

    // loader mappings
    int arow[4], astore[4], boff[4], bstore[4];
#pragma unroll
    for (int i = 0; i < 4; i++) {
        int idx = tid + i * 128;
        int ar = idx >> 3, aq = idx & 7;              // A: 64 rows x 8 quads
        arow[i]   = rowbase[ar] + aq * 4;
        astore[i] = ar * QS + aq * 4;
        int bk = idx >> 4, bc = idx & 15;             // B: 32 rows x 16 quads
        boff[i]   = bk * ldb + coff + bc * 4;
        bstore[i] = bk * BSS + bc * 4;
    }

    float acc[2][4][4];
#pragma unroll
    for (int m = 0; m < 2; m++)
#pragma unroll
        for (int n = 0; n < 4; n++)
#pragma unroll
            for (int e = 0; e < 4; e++) acc[m][n][e] = 0.f;

    for (int k0 = 0; k0 < D_MODEL; k0 += 32) {
        float4 av[4], bv[4];
#pragma unroll
        for (int i = 0; i < 4; i++) {
            av[i] = *(const float4*)(x + arow[i] + k0);
            bv[i] = *(const float4*)(Bsrc + boff[i] + (size_t)k0 * ldb);
        }
        __syncthreads();
#pragma unroll
        for (int i = 0; i < 4; i++) {
            float* ap = As + astore[i];
            ap[0] = __uint_as_float(f2tf(av[i].x));
            ap[1] = __uint_as_float(f2tf(av[i].y));
            ap[2] = __uint_as_float(f2tf(av[i].z));
            ap[3] = __uint_as_float(f2tf(av[i].w));
            float* bp = Bs + bstore[i];
            bp[0] = __uint_as_float(f2tf(bv[i].x));
            bp[1] = __uint_as_float(f2tf(bv[i].y));
            bp[2] = __uint_as_float(f2tf(bv[i].z));
            bp[3] = __uint_as_float(f2tf(bv[i].w));
        }
        __syncthreads();
#pragma unroll
        for (int kk = 0; kk < 4; kk++) {
            unsigned afr[2][4];
#pragma unroll
            for (int mt = 0; mt < 2; mt++) {
                int mr = wm * 32 + mt * 16;
                afr[mt][0] = fbits(As[(mr + g)     * QS + kk * 8 + t]);
                afr[mt][1] = fbits(As[(mr + g + 8) * QS + kk * 8 + t]);
                afr[mt][2] = fbits(As[(mr + g)     * QS + kk * 8 + t + 4]);
                afr[mt][3] = fbits(As[(mr + g + 8) * QS + kk * 8 + t + 4]);
            }
#pragma unroll
            for (int nt = 0; nt < 4; nt++) {
                int nc = wn * 32 + nt * 8;
                unsigned bfr[2];
                bfr[0] = fbits(Bs[(kk * 8 + t)     * BSS + nc + g]);
                bfr[1] = fbits(Bs[(kk * 8 + t + 4) * BSS + nc + g]);
                mma_tf32(acc[0][nt], afr[0], bfr);
                mma_tf32(acc[1][nt], afr[1], bfr);
            }
        }
    }

    const float scale = 0.17677669529663687f;
#pragma unroll
    for (int mt = 0; mt < 2; mt++) {
#pragma unroll
        for (int e = 0; e < 2; e++) {
            int r = r0 + wm * 32 + mt * 16 + g + e * 8;
            int w = r / NTOK;  int tok = r - w * NTOK;
#pragma unroll
            for (int nt = 0; nt < 4; nt++) {
#pragma unroll
                for (int c2 = 0; c2 < 2; c2++) {
                    int nc = c0 + wn * 32 + nt * 8 + 2 * t + c2;
                    float va = acc[mt][nt][e * 2 + c2];
                    if (nc < D_MODEL) {
                        int h = nc >> 5, c = nc & 31;
                        g_q[(((size_t)w * HEADS + h) * NTOK + tok) * DH + c] =
                            __uint_as_float(f2tf((va + __ldg(bq + nc)) * scale));
                    } else {
                        int kc = nc - D_MODEL;
                        float val = va + __ldg(bkv + kc);
                        val = __uint_as_float(f2tf(val));
                        if (kc < D_MODEL) {
                            int h = kc >> 5, c = kc & 31;
                            g_k[(((size_t)w * HEADS + h) * NTOK + tok) * DH + c] = val;
                        } else {
                            int vc = kc - D_MODEL;
                            int h = vc >> 5, c = vc & 31;
                            g_v[(((size_t)w * HEADS + h) * NTOK + tok) * DH + c] = val;
                        }
                    }
                }
            }
        }
    }
}

// ===========================================================================
// Kernel 2: window attention (tf32 tensor cores). One CTA per (window, head).
// ===========================================================================
__global__ __launch_bounds__(256) void attn_tc(const float* __restrict__ bias_table)
{
    extern __shared__ float sm[];
    float* Qs   = sm;                       // NPAD x 36
    float* Ks   = sm + NPAD * QS;           // NPAD x 36
    float* Vs   = Ks + NPAD * QS;           // NPAD x 40
    float* Sb   = Vs + NPAD * VS;           // 64 x 308
    int*   Ci_s = (int*)(Sb + 64 * SS);     // NPAD
    int*   bJ   = Ci_s + NPAD;              // NPAD
    float* rinv = (float*)(bJ + NPAD);      // 64

    const int wh = blockIdx.x;
    const int w  = wh >> 3, h = wh & 7;
    const int tid = threadIdx.x;
    const int lane = tid & 31, wid = tid >> 5;
    const int g = lane >> 2, t = lane & 3;

    // ---- prologue: stage Q/K/V, zero pads, index tables ----
    const float* qg = g_q + (size_t)wh * NTOK * DH;
    const float* kg = g_k + (size_t)wh * NTOK * DH;
    const float* vg = g_v + (size_t)wh * NTOK * DH;
    for (int idx = tid; idx < NTOK * 8; idx += 256) {
        int row = idx >> 3, q4 = (idx & 7) * 4;
        float4 qa = *(const float4*)(qg + row * DH + q4);
        float4 ka = *(const float4*)(kg + row * DH + q4);
        float4 va = *(const float4*)(vg + row * DH + q4);
        *(float4*)(Qs + row * QS + q4) = qa;
        *(float4*)(Ks + row * QS + q4) = ka;
        *(float4*)(Vs + row * VS + q4) = va;
    }
    for (int idx = tid; idx < (NPAD - NTOK) * 8; idx += 256) {
        int row = NTOK + (idx >> 3), q4 = (idx & 7) * 4;
        float4 z = make_float4(0.f, 0.f, 0.f, 0.f);
        *(float4*)(Qs + row * QS + q4) = z;
        *(float4*)(Ks + row * QS + q4) = z;
        *(float4*)(Vs + row * VS + q4) = z;
    }
    for (int i = tid; i < NPAD; i += 256) {
        int ii = min(i, NTOK - 1);
        int li = ii / 49, r2 = ii - li * 49, ai = r2 / 7, bi = r2 - ai * 7;
        Ci_s[i] = (li + 5) * 169 + (ai + 6) * 13 + (bi + 6);
        bJ[i]   = li * 169 + ai * 13 + bi;
    }
    __syncthreads();

    // ---- chunk loop over queries ----
    for (int mc = 0; mc < 5; mc++) {
        const int m_base  = mc * 64;
        const int tiles_m = min(4, NT16 - mc * 4);

        // S = Q Kt + bias : warp (wid&3)=m-tile, (wid>>2)=n half
        {
            int mt = wid & 3;
            int ns = (wid >> 2) * 19;
            if (mt < tiles_m) {
                unsigned a[4][4];
                int mr = m_base + mt * 16;
#pragma unroll
                for (int kk = 0; kk < 4; kk++) {
                    a[kk][0] = fbits(Qs[(mr + g)     * QS + kk * 8 + t]);
                    a[kk][1] = fbits(Qs[(mr + g + 8) * QS + kk * 8 + t]);
                    a[kk][2] = fbits(Qs[(mr + g)     * QS + kk * 8 + t + 4]);
                    a[kk][3] = fbits(Qs[(mr + g + 8) * QS + kk * 8 + t + 4]);
                }
                int Ci0 = Ci_s[mr + g], Ci1 = Ci_s[mr + g + 8];
                for (int nt = ns; nt < ns + 19; nt++) {
                    float c[4] = {0.f, 0.f, 0.f, 0.f};
#pragma unroll
                    for (int kk = 0; kk < 4; kk++) {
                        unsigned b[2];
                        b[0] = fbits(Ks[(nt * 8 + g) * QS + kk * 8 + t]);
                        b[1] = fbits(Ks[(nt * 8 + g) * QS + kk * 8 + t + 4]);
                        mma_tf32(c, a[kk], b);
                    }
                    int j0 = nt * 8 + 2 * t;
                    float s00 = c[0] + __ldg(bias_table + (size_t)(Ci0 - bJ[j0])     * HEADS + h);
                    float s01 = c[1] + __ldg(bias_table + (size_t)(Ci0 - bJ[j0 + 1]) * HEADS + h);
                    float s10 = c[2] + __ldg(bias_table + (size_t)(Ci1 - bJ[j0])     * HEADS + h);
                    float s11 = c[3] + __ldg(bias_table + (size_t)(Ci1 - bJ[j0 + 1]) * HEADS + h);
                    *(float2*)(Sb + (mt * 16 + g)     * SS + j0) = make_float2(s00, s01);
                    *(float2*)(Sb + (mt * 16 + g + 8) * SS + j0) = make_float2(s10, s11);
                }
            }
        }
        __syncthreads();

        // softmax over rows of Sb (4 lanes per row)
        {
            int row = tid >> 2, part = tid & 3;
            if (row < tiles_m * 16) {
                float* Srow = Sb + row * SS;
                int j0 = part * 76;
                float mx = -1e30f;
#pragma unroll 4
                for (int jj = 0; jj < 76; jj++) {
                    int j = j0 + jj;
                    if (j < NTOK) mx = fmaxf(mx, Srow[j]);
                }
                mx = fmaxf(mx, __shfl_xor_sync(0xffffffffu, mx, 1));
                mx = fmaxf(mx, __shfl_xor_sync(0xffffffffu, mx, 2));
                float sum = 0.f;
#pragma unroll 4
                for (int jj = 0; jj < 76; jj++) {
                    int j = j0 + jj;
                    float p = 0.f;
                    if (j < NTOK) { p = __expf(Srow[j] - mx); sum += p; }
                    Srow[j] = __uint_as_float(f2tf(p));
                }
                sum += __shfl_xor_sync(0xffffffffu, sum, 1);
                sum += __shfl_xor_sync(0xffffffffu, sum, 2);
                if (part == 0) rinv[row] = 1.f / sum;
            }
        }
        __syncthreads();

        // O = P V : warp (wid&3)=m-tile, (wid>>2)*2 = n-tile base
        {
            int mt  = wid & 3;
            int ntb = (wid >> 2) * 2;
            if (mt < tiles_m) {
                float c[2][4];
#pragma unroll
                for (int q = 0; q < 2; q++)
#pragma unroll
                    for (int e = 0; e < 4; e++) c[q][e] = 0.f;
                for (int kk = 0; kk < 38; kk++) {
                    unsigned a[4];
                    a[0] = fbits(Sb[(mt * 16 + g)     * SS + kk * 8 + t]);
                    a[1] = fbits(Sb[(mt * 16 + g + 8) * SS + kk * 8 + t]);
                    a[2] = fbits(Sb[(mt * 16 + g)     * SS + kk * 8 + t + 4]);
                    a[3] = fbits(Sb[(mt * 16 + g + 8) * SS + kk * 8 + t + 4]);
#pragma unroll
                    for (int q = 0; q < 2; q++) {
                        int n0 = (ntb + q) * 8;
                        unsigned b[2];
                        b[0] = fbits(Vs[(kk * 8 + t)     * VS + n0 + g]);
                        b[1] = fbits(Vs[(kk * 8 + t + 4) * VS + n0 + g]);
                        mma_tf32(c[q], a, b);
                    }
                }
#pragma unroll
                for (int e = 0; e < 2; e++) {
                    int r_l = mt * 16 + g + e * 8;
                    int iq  = m_base + r_l;
                    if (iq < NTOK) {
                        float inv = rinv[r_l];
                        float* dst = g_ctx + ((size_t)w * NTOK + iq) * D_MODEL + h * DH;
#pragma unroll
                        for (int q = 0; q < 2; q++) {
                            int cc = (ntb + q) * 8 + 2 * t;
                            dst[cc]     = __uint_as_float(f2tf(c[q][e * 2 + 0] * inv));
                            dst[cc + 1] = __uint_as_float(f2tf(c[q][e * 2 + 1] * inv));
                        }
                    }
                }
            }
        }
        __syncthreads();
    }
}

// ===========================================================================
// Kernel 3: output projection (tf32), scatter epilogue.
// ===========================================================================
__global__ __launch_bounds__(128) void out_gemm_tc(
    const float* __restrict__ Wout, float* __restrict__ out)
{
    __shared__ float As[64 * QS];
    __shared__ float Bs[32 * BSS];
    __shared__ int   rowbase[64];

    const int tid  = threadIdx.x;
    const int lane = tid & 31, wid = tid >> 5;
    const int wm = wid & 1, wn = wid >> 1;
    const int g = lane >> 2, t = lane & 3;
    const int r0 = blockIdx.x * 64;
    const int c0 = blockIdx.y * 64;

    if (tid < 64) rowbase[tid] = x_offset(r0 + tid);
    __syncthreads();

    int aoff[4], astore[4], boff[4], bstore[4];
#pragma unroll
    for (int i = 0; i < 4; i++) {
        int idx = tid + i * 128;
        int ar = idx >> 3, aq = idx & 7;
        aoff[i]   = (r0 + ar) * D_MODEL + aq * 4;
        astore[i] = ar * QS + aq * 4;
        int bk = idx >> 4, bc = idx & 15;
        boff[i]   = bk * D_MODEL + c0 + bc * 4;
        bstore[i] = bk * BSS + bc * 4;
    }

    float acc[2][4][4];
#pragma unroll
    for (int m = 0; m < 2; m++)
#pragma unroll
        for (int n = 0; n < 4; n++)
#pragma unroll
            for (int e = 0; e < 4; e++) acc[m][n][e] = 0.f;

    for (int k0 = 0; k0 < D_MODEL; k0 += 32) {
        float4 av[4], bv[4];
#pragma unroll
        for (int i = 0; i < 4; i++) {
            av[i] = *(const float4*)(g_ctx + aoff[i] + k0);
            bv[i] = *(const float4*)(Wout + boff[i] + (size_t)k0 * D_MODEL);
        }
        __syncthreads();
#pragma unroll
        for (int i = 0; i < 4; i++) {
            *(float4*)(As + astore[i]) = av[i];   // already tf32-rounded
            float* bp = Bs + bstore[i];
            bp[0] = __uint_as_float(f2tf(bv[i].x));
            bp[1] = __uint_as_float(f2tf(bv[i].y));
            bp[2] = __uint_as_float(f2tf(bv[i].z));
            bp[3] = __uint_as_float(f2tf(bv[i].w));
        }
        __syncthreads();
#pragma unroll
        for (int kk = 0; kk < 4; kk++) {
            unsigned afr[2][4];
#pragma unroll
            for (int mt = 0; mt < 2; mt++) {
                int mr = wm * 32 + mt * 16;
                afr[mt][0] = fbits(As[(mr + g)     * QS + kk * 8 + t]);
                afr[mt][1] = fbits(As[(mr + g + 8) * QS + kk * 8 + t]);
                afr[mt][2] = fbits(As[(mr + g)     * QS + kk * 8 + t + 4]);
                afr[mt][3] = fbits(As[(mr + g + 8) * QS + kk * 8 + t + 4]);
            }
#pragma unroll
            for (int nt = 0; nt < 4; nt++) {
                int nc = wn * 32 + nt * 8;
                unsigned bfr[2];
                bfr[0] = fbits(Bs[(kk * 8 + t)     * BSS + nc + g]);
                bfr[1] = fbits(Bs[(kk * 8 + t + 4) * BSS + nc + g]);
                mma_tf32(acc[0][nt], afr[0], bfr);
                mma_tf32(acc[1][nt], afr[1], bfr);
            }
        }
    }

#pragma unroll
    for (int mt = 0; mt < 2; mt++) {
#pragma unroll
        for (int e = 0; e < 2; e++) {
            int rl = wm * 32 + mt * 16 + g + e * 8;
            int xb = rowbase[rl];
#pragma unroll
            for (int nt = 0; nt < 4; nt++) {
                int cc = c0 + wn * 32 + nt * 8 + 2 * t;
                *(float2*)(out + xb + cc) =
                    make_float2(acc[mt][nt][e * 2 + 0], acc[mt][nt][e * 2 + 1]);
            }
        }
    }
}

// ---------------------------------------------------------------------------
// Launch
// ---------------------------------------------------------------------------
extern "C" void kernel_launch(void* const* d_in, const int* in_sizes, int n_in,
                              void* d_out, int out_size)
{
    const float* x    = (const float*)d_in[0];
    const float* Wq   = (const float*)d_in[1];
    const float* bq   = (const float*)d_in[2];
    const float* Wkv  = (const float*)d_in[3];
    const float* bkv  = (const float*)d_in[4];
    const float* Wout = (const float*)d_in[5];
    const float* bias = (const float*)d_in[6];
    float* out = (float*)d_out;

    // attention dynamic smem: Q,K (NPAD*36) + V (NPAD*40) + S (64*308) + tables
    const int attn_smem = (NPAD * QS * 2 + NPAD * VS + 64 * SS + NPAD * 2 + 64) * 4;
    cudaFuncSetAttribute(attn_tc,
                         cudaFuncAttributeMaxDynamicSharedMemorySize, attn_smem);

    dim3 g1(M_ROWS / 64, QKV_N / 64);     // (1323, 12)
    qkv_gemm_tc<<<g1, 128>>>(x, Wq, bq, Wkv, bkv);

    attn_tc<<<NWIN * HEADS, 256, attn_smem>>>(bias);

    dim3 g2(M_ROWS / 64, D_MODEL / 64);   // (1323, 4)
    out_gemm_tc<<<g2, 128>>>(Wout, out);
}

// round 6
// speedup vs baseline: 3.1208x; 1.7040x over previous
#include <cuda_runtime.h>

// ---------------------------------------------------------------------------
// Problem constants
// ---------------------------------------------------------------------------
#define NTOK    294
#define NPAD    304            // padded tokens (19 * 16)
#define NT16    19
#define NWIN    288
#define D_MODEL 256
#define HEADS   8
#define DH      32
#define M_ROWS  (NWIN * NTOK)  // 84672
#define QKV_N   768

// smem strides (floats), conflict-free for the tf32 fragment access patterns
#define QS   36   // K rows (32 cols): banks 4g+t bijective
#define VS   40   // V rows (32 cols): banks 8t+g bijective
#define BS2  136  // GEMM B tile rows (128 cols): banks 8t+g bijective

// ---------------------------------------------------------------------------
// Scratch
// ---------------------------------------------------------------------------
__device__ float g_q  [(size_t)NWIN * HEADS * NTOK * DH];
__device__ float g_k  [(size_t)NWIN * HEADS * NTOK * DH];
__device__ float g_v  [(size_t)NWIN * HEADS * NTOK * DH];
__device__ float g_ctx[(size_t)M_ROWS * D_MODEL];

__device__ __forceinline__ int x_offset(int r) {
    int w  = r / NTOK;  int t   = r - w * NTOK;
    int bb = w / 144;   int rem = w - bb * 144;
    int gx = rem / 12;  int gy  = rem - gx * 12;
    int l  = t / 49;    int t2  = t - l * 49;
    int w1 = t2 / 7;    int w2  = t2 - w1 * 7;
    return (((((bb * 6 + l) * 12 + gx) * 12 + gy) * 7 + w1) * 7 + w2) * D_MODEL;
}

__device__ __forceinline__ unsigned f2tf(float f) {
    unsigned u;
    asm("cvt.rna.tf32.f32 %0, %1;" : "=r"(u) : "f"(f));
    return u;
}
__device__ __forceinline__ unsigned fbits(float f) { return __float_as_uint(f); }

__device__ __forceinline__ void mma_tf32(float c[4], const unsigned a[4], const unsigned b[2]) {
    asm volatile(
        "mma.sync.aligned.m16n8k8.row.col.f32.tf32.tf32.f32 "
        "{%0,%1,%2,%3}, {%4,%5,%6,%7}, {%8,%9}, {%0,%1,%2,%3};"
        : "+f"(c[0]), "+f"(c[1]), "+f"(c[2]), "+f"(c[3])
        : "r"(a[0]), "r"(a[1]), "r"(a[2]), "r"(a[3]), "r"(b[0]), "r"(b[1]));
}

// ===========================================================================
// Kernel 1: QKV projection.  CTA tile 64x128, 4 warps of 32x64, BK=32.
// ===========================================================================
__global__ __launch_bounds__(128) void qkv_gemm_tc(
    const float* __restrict__ x,
    const float* __restrict__ Wq,  const float* __restrict__ bq,
    const float* __restrict__ Wkv, const float* __restrict__ bkv)
{
    __shared__ float As[64 * QS];    // [m][k] stride 36
    __shared__ float Bs[32 * BS2];   // [k][n] stride 136 (128 cols)
    __shared__ int   rowbase[64];

    const int tid  = threadIdx.x;
    const int lane = tid & 31, wid = tid >> 5;
    const int wm = wid & 1, wn = wid >> 1;
    const int g = lane >> 2, t = lane & 3;
    const int r0 = blockIdx.x * 64;
    const int c0 = blockIdx.y * 128;

    const float* Bsrc; int ldb, coff;
    if (c0 < D_MODEL) { Bsrc = Wq;  ldb = D_MODEL;     coff = c0; }
    else              { Bsrc = Wkv; ldb = 2 * D_MODEL; coff = c0 - D_MODEL; }

    if (tid < 64) rowbase[tid] = x_offset(r0 + tid);
    __syncthreads();

    // loader mappings: A 64x32 (4 float4/thr), B 32x128 (8 float4/thr)
    int arow[4], astore[4], boff[8], bstore[8];
#pragma unroll
    for (int i = 0; i < 4; i++) {
        int idx = tid + i * 128;
        int ar = idx >> 3, aq = idx & 7;
        arow[i]   = rowbase[ar] + aq * 4;
        astore[i] = ar * QS + aq * 4;
    }
#pragma unroll
    for (int i = 0; i < 8; i++) {
        int idx = tid + i * 128;
        int bk = idx >> 5, bc = idx & 31;
        boff[i]   = bk * ldb + coff + bc * 4;
        bstore[i] = bk * BS2 + bc * 4;
    }

    float acc[2][8][4];
#pragma unroll
    for (int m = 0; m < 2; m++)
#pragma unroll
        for (int n = 0; n < 8; n++)
#pragma unroll
            for (int e = 0; e < 4; e++) acc[m][n][e] = 0.f;

    for (int k0 = 0; k0 < D_MODEL; k0 += 32) {
        float4 av[4], bv[8];
#pragma unroll
        for (int i = 0; i < 4; i++)
            av[i] = *(const float4*)(x + arow[i] + k0);
#pragma unroll
        for (int i = 0; i < 8; i++)
            bv[i] = *(const float4*)(Bsrc + boff[i] + (size_t)k0 * ldb);
        __syncthreads();
#pragma unroll
        for (int i = 0; i < 4; i++) {
            float* ap = As + astore[i];
            ap[0] = __uint_as_float(f2tf(av[i].x));
            ap[1] = __uint_as_float(f2tf(av[i].y));
            ap[2] = __uint_as_float(f2tf(av[i].z));
            ap[3] = __uint_as_float(f2tf(av[i].w));
        }
#pragma unroll
        for (int i = 0; i < 8; i++) {
            float* bp = Bs + bstore[i];
            bp[0] = __uint_as_float(f2tf(bv[i].x));
            bp[1] = __uint_as_float(f2tf(bv[i].y));
            bp[2] = __uint_as_float(f2tf(bv[i].z));
            bp[3] = __uint_as_float(f2tf(bv[i].w));
        }
        __syncthreads();
#pragma unroll
        for (int kk = 0; kk < 4; kk++) {
            unsigned afr[2][4];
#pragma unroll
            for (int mt = 0; mt < 2; mt++) {
                int mr = wm * 32 + mt * 16;
                afr[mt][0] = fbits(As[(mr + g)     * QS + kk * 8 + t]);
                afr[mt][1] = fbits(As[(mr + g + 8) * QS + kk * 8 + t]);
                afr[mt][2] = fbits(As[(mr + g)     * QS + kk * 8 + t + 4]);
                afr[mt][3] = fbits(As[(mr + g + 8) * QS + kk * 8 + t + 4]);
            }
#pragma unroll
            for (int nt = 0; nt < 8; nt++) {
                int nc = wn * 64 + nt * 8;
                unsigned bfr[2];
                bfr[0] = fbits(Bs[(kk * 8 + t)     * BS2 + nc + g]);
                bfr[1] = fbits(Bs[(kk * 8 + t + 4) * BS2 + nc + g]);
                mma_tf32(acc[0][nt], afr[0], bfr);
                mma_tf32(acc[1][nt], afr[1], bfr);
            }
        }
    }

    const float scale = 0.17677669529663687f;
#pragma unroll
    for (int mt = 0; mt < 2; mt++) {
#pragma unroll
        for (int e = 0; e < 2; e++) {
            int r = r0 + wm * 32 + mt * 16 + g + e * 8;
            int w = r / NTOK;  int tok = r - w * NTOK;
#pragma unroll
            for (int nt = 0; nt < 8; nt++) {
#pragma unroll
                for (int c2 = 0; c2 < 2; c2++) {
                    int nc = c0 + wn * 64 + nt * 8 + 2 * t + c2;
                    float va = acc[mt][nt][e * 2 + c2];
                    if (nc < D_MODEL) {
                        int h = nc >> 5, c = nc & 31;
                        g_q[(((size_t)w * HEADS + h) * NTOK + tok) * DH + c] =
                            __uint_as_float(f2tf((va + __ldg(bq + nc)) * scale));
                    } else {
                        int kc = nc - D_MODEL;
                        float val = __uint_as_float(f2tf(va + __ldg(bkv + kc)));
                        if (kc < D_MODEL) {
                            int h = kc >> 5, c = kc & 31;
                            g_k[(((size_t)w * HEADS + h) * NTOK + tok) * DH + c] = val;
                        } else {
                            int vc = kc - D_MODEL;
                            int h = vc >> 5, c = vc & 31;
                            g_v[(((size_t)w * HEADS + h) * NTOK + tok) * DH + c] = val;
                        }
                    }
                }
            }
        }
    }
}

// ===========================================================================
// Kernel 2: register-resident flash attention. One CTA per (window, head),
// one warp per 16-query tile. No S buffer, no phase barriers, 2 CTAs/SM.
// ===========================================================================
__global__ __launch_bounds__(256, 2) void attn_flash(const float* __restrict__ bias_table)
{
    extern __shared__ float sm[];
    float* Ks = sm;                       // NPAD x 36
    float* Vs = sm + NPAD * QS;           // NPAD x 40
    int*   bJ = (int*)(Vs + NPAD * VS);   // NPAD

    const int wh = blockIdx.x;
    const int w  = wh >> 3, h = wh & 7;
    const int tid = threadIdx.x;
    const int lane = tid & 31, wid = tid >> 5;
    const int g = lane >> 2, t = lane & 3;

    // ---- stage K/V, zero pad rows, bJ table ----
    const float* kg = g_k + (size_t)wh * NTOK * DH;
    const float* vg = g_v + (size_t)wh * NTOK * DH;
    for (int idx = tid; idx < NTOK * 8; idx += 256) {
        int row = idx >> 3, q4 = (idx & 7) * 4;
        *(float4*)(Ks + row * QS + q4) = *(const float4*)(kg + row * DH + q4);
        *(float4*)(Vs + row * VS + q4) = *(const float4*)(vg + row * DH + q4);
    }
    for (int idx = tid; idx < (NPAD - NTOK) * 8; idx += 256) {
        int row = NTOK + (idx >> 3), q4 = (idx & 7) * 4;
        float4 z = make_float4(0.f, 0.f, 0.f, 0.f);
        *(float4*)(Ks + row * QS + q4) = z;
        *(float4*)(Vs + row * VS + q4) = z;
    }
    for (int j = tid; j < NPAD; j += 256) {
        int jj = min(j, NTOK - 1);
        int l = jj / 49, r2 = jj - l * 49, a = r2 / 7, b = r2 - a * 7;
        bJ[j] = l * 169 + a * 13 + b;
    }
    __syncthreads();

    const float* qg = g_q + (size_t)wh * NTOK * DH;

    for (int mt = wid; mt < NT16; mt += 8) {
        const int r0 = mt * 16 + g;
        const int r1 = r0 + 8;
        const int rr0 = min(r0, NTOK - 1), rr1 = min(r1, NTOK - 1);

        int l0 = rr0 / 49, x0 = rr0 - l0 * 49, a0 = x0 / 7, b0 = x0 - a0 * 7;
        const int Ci0 = (l0 + 5) * 169 + (a0 + 6) * 13 + (b0 + 6);
        int l1 = rr1 / 49, x1 = rr1 - l1 * 49, a1 = x1 / 7, b1 = x1 - a1 * 7;
        const int Ci1 = (l1 + 5) * 169 + (a1 + 6) * 13 + (b1 + 6);

        // Q A-fragments straight from global (tiny, L2-hot)
        unsigned qa[4][4];
#pragma unroll
        for (int kk = 0; kk < 4; kk++) {
            qa[kk][0] = fbits(__ldg(qg + rr0 * DH + kk * 8 + t));
            qa[kk][1] = fbits(__ldg(qg + rr1 * DH + kk * 8 + t));
            qa[kk][2] = fbits(__ldg(qg + rr0 * DH + kk * 8 + t + 4));
            qa[kk][3] = fbits(__ldg(qg + rr1 * DH + kk * 8 + t + 4));
        }

        float O[4][4];
#pragma unroll
        for (int ot = 0; ot < 4; ot++)
#pragma unroll
            for (int e = 0; e < 4; e++) O[ot][e] = 0.f;
        float sum0 = 0.f, sum1 = 0.f;

        for (int nt = 0; nt < 37; nt++) {
            // S tile: 16x8
            float c[4] = {0.f, 0.f, 0.f, 0.f};
#pragma unroll
            for (int kk = 0; kk < 4; kk++) {
                unsigned b[2];
                b[0] = fbits(Ks[(nt * 8 + g) * QS + kk * 8 + t]);
                b[1] = fbits(Ks[(nt * 8 + g) * QS + kk * 8 + t + 4]);
                mma_tf32(c, qa[kk], b);
            }

            // bias + exp (no max subtraction: |s| is O(1) by construction)
            const int j0 = nt * 8 + 2 * t, j1 = j0 + 1;
            const int bj0 = bJ[j0], bj1 = bJ[j1];
            float bi00 = __ldg(bias_table + (size_t)(Ci0 - bj0) * HEADS + h);
            float bi01 = __ldg(bias_table + (size_t)(Ci0 - bj1) * HEADS + h);
            float bi10 = __ldg(bias_table + (size_t)(Ci1 - bj0) * HEADS + h);
            float bi11 = __ldg(bias_table + (size_t)(Ci1 - bj1) * HEADS + h);
            float p0 = (j0 < NTOK) ? __expf(c[0] + bi00) : 0.f;
            float p1 = (j1 < NTOK) ? __expf(c[1] + bi01) : 0.f;
            float p2 = (j0 < NTOK) ? __expf(c[2] + bi10) : 0.f;
            float p3 = (j1 < NTOK) ? __expf(c[3] + bi11) : 0.f;
            sum0 += p0 + p1;
            sum1 += p2 + p3;

            unsigned u0 = f2tf(p0), u1 = f2tf(p1), u2 = f2tf(p2), u3 = f2tf(p3);

            // C-frag (cols 2t,2t+1) -> A-frag (k = t, t+4) via shuffles
            const int src1 = (lane & 28) | (t >> 1);
            const int src2 = src1 + 2;
            unsigned s0a = __shfl_sync(0xffffffffu, u0, src1);
            unsigned s1a = __shfl_sync(0xffffffffu, u1, src1);
            unsigned s2a = __shfl_sync(0xffffffffu, u2, src1);
            unsigned s3a = __shfl_sync(0xffffffffu, u3, src1);
            unsigned s0b = __shfl_sync(0xffffffffu, u0, src2);
            unsigned s1b = __shfl_sync(0xffffffffu, u1, src2);
            unsigned s2b = __shfl_sync(0xffffffffu, u2, src2);
            unsigned s3b = __shfl_sync(0xffffffffu, u3, src2);
            unsigned pa[4];
            pa[0] = (t & 1) ? s1a : s0a;   // (row g,   k=t)
            pa[1] = (t & 1) ? s3a : s2a;   // (row g+8, k=t)
            pa[2] = (t & 1) ? s1b : s0b;   // (row g,   k=t+4)
            pa[3] = (t & 1) ? s3b : s2b;   // (row g+8, k=t+4)

            // O += P V  (k = this 8-key group)
#pragma unroll
            for (int ot = 0; ot < 4; ot++) {
                unsigned vb[2];
                vb[0] = fbits(Vs[(nt * 8 + t)     * VS + ot * 8 + g]);
                vb[1] = fbits(Vs[(nt * 8 + t + 4) * VS + ot * 8 + g]);
                mma_tf32(O[ot], pa, vb);
            }
        }

        // row sums across the 4-lane t-group
        sum0 += __shfl_xor_sync(0xffffffffu, sum0, 1);
        sum0 += __shfl_xor_sync(0xffffffffu, sum0, 2);
        sum1 += __shfl_xor_sync(0xffffffffu, sum1, 1);
        sum1 += __shfl_xor_sync(0xffffffffu, sum1, 2);
        const float inv0 = 1.f / sum0, inv1 = 1.f / sum1;

        if (r0 < NTOK) {
            float* d = g_ctx + ((size_t)w * NTOK + r0) * D_MODEL + h * DH;
#pragma unroll
            for (int ot = 0; ot < 4; ot++) {
                float2 v2 = make_float2(__uint_as_float(f2tf(O[ot][0] * inv0)),
                                        __uint_as_float(f2tf(O[ot][1] * inv0)));
                *(float2*)(d + ot * 8 + 2 * t) = v2;
            }
        }
        if (r1 < NTOK) {
            float* d = g_ctx + ((size_t)w * NTOK + r1) * D_MODEL + h * DH;
#pragma unroll
            for (int ot = 0; ot < 4; ot++) {
                float2 v2 = make_float2(__uint_as_float(f2tf(O[ot][2] * inv1)),
                                        __uint_as_float(f2tf(O[ot][3] * inv1)));
                *(float2*)(d + ot * 8 + 2 * t) = v2;
            }
        }
    }
}

// ===========================================================================
// Kernel 3: output projection.  CTA 64x128, warp 32x64, scatter epilogue.
// ===========================================================================
__global__ __launch_bounds__(128) void out_gemm_tc(
    const float* __restrict__ Wout, float* __restrict__ out)
{
    __shared__ float As[64 * QS];
    __shared__ float Bs[32 * BS2];
    __shared__ int   rowbase[64];

    const int tid  = threadIdx.x;
    const int lane = tid & 31, wid = tid >> 5;
    const int wm = wid & 1, wn = wid >> 1;
    const int g = lane >> 2, t = lane & 3;
    const int r0 = blockIdx.x * 64;
    const int c0 = blockIdx.y * 128;

    if (tid < 64) rowbase[tid] = x_offset(r0 + tid);
    __syncthreads();

    int aoff[4], astore[4], boff[8], bstore[8];
#pragma unroll
    for (int i = 0; i < 4; i++) {
        int idx = tid + i * 128;
        int ar = idx >> 3, aq = idx & 7;
        aoff[i]   = (r0 + ar) * D_MODEL + aq * 4;
        astore[i] = ar * QS + aq * 4;
    }
#pragma unroll
    for (int i = 0; i < 8; i++) {
        int idx = tid + i * 128;
        int bk = idx >> 5, bc = idx & 31;
        boff[i]   = bk * D_MODEL + c0 + bc * 4;
        bstore[i] = bk * BS2 + bc * 4;
    }

    float acc[2][8][4];
#pragma unroll
    for (int m = 0; m < 2; m++)
#pragma unroll
        for (int n = 0; n < 8; n++)
#pragma unroll
            for (int e = 0; e < 4; e++) acc[m][n][e] = 0.f;

    for (int k0 = 0; k0 < D_MODEL; k0 += 32) {
        float4 av[4], bv[8];
#pragma unroll
        for (int i = 0; i < 4; i++)
            av[i] = *(const float4*)(g_ctx + aoff[i] + k0);
#pragma unroll
        for (int i = 0; i < 8; i++)
            bv[i] = *(const float4*)(Wout + boff[i] + (size_t)k0 * D_MODEL);
        __syncthreads();
#pragma unroll
        for (int i = 0; i < 4; i++)
            *(float4*)(As + astore[i]) = av[i];   // already tf32-rounded
#pragma unroll
        for (int i = 0; i < 8; i++) {
            float* bp = Bs + bstore[i];
            bp[0] = __uint_as_float(f2tf(bv[i].x));
            bp[1] = __uint_as_float(f2tf(bv[i].y));
            bp[2] = __uint_as_float(f2tf(bv[i].z));
            bp[3] = __uint_as_float(f2tf(bv[i].w));
        }
        __syncthreads();
#pragma unroll
        for (int kk = 0; kk < 4; kk++) {
            unsigned afr[2][4];
#pragma unroll
            for (int mt = 0; mt < 2; mt++) {
                int mr = wm * 32 + mt * 16;
                afr[mt][0] = fbits(As[(mr + g)     * QS + kk * 8 + t]);
                afr[mt][1] = fbits(As[(mr + g + 8) * QS + kk * 8 + t]);
                afr[mt][2] = fbits(As[(mr + g)     * QS + kk * 8 + t + 4]);
                afr[mt][3] = fbits(As[(mr + g + 8) * QS + kk * 8 + t + 4]);
            }
#pragma unroll
            for (int nt = 0; nt < 8; nt++) {
                int nc = wn * 64 + nt * 8;
                unsigned bfr[2];
                bfr[0] = fbits(Bs[(kk * 8 + t)     * BS2 + nc + g]);
                bfr[1] = fbits(Bs[(kk * 8 + t + 4) * BS2 + nc + g]);
                mma_tf32(acc[0][nt], afr[0], bfr);
                mma_tf32(acc[1][nt], afr[1], bfr);
            }
        }
    }

#pragma unroll
    for (int mt = 0; mt < 2; mt++) {
#pragma unroll
        for (int e = 0; e < 2; e++) {
            int rl = wm * 32 + mt * 16 + g + e * 8;
            int xb = rowbase[rl];
#pragma unroll
            for (int nt = 0; nt < 8; nt++) {
                int cc = c0 + wn * 64 + nt * 8 + 2 * t;
                *(float2*)(out + xb + cc) =
                    make_float2(acc[mt][nt][e * 2 + 0], acc[mt][nt][e * 2 + 1]);
            }
        }
    }
}

// ---------------------------------------------------------------------------
// Launch
// ---------------------------------------------------------------------------
extern "C" void kernel_launch(void* const* d_in, const int* in_sizes, int n_in,
                              void* d_out, int out_size)
{
    const float* x    = (const float*)d_in[0];
    const float* Wq   = (const float*)d_in[1];
    const float* bq   = (const float*)d_in[2];
    const float* Wkv  = (const float*)d_in[3];
    const float* bkv  = (const float*)d_in[4];
    const float* Wout = (const float*)d_in[5];
    const float* bias = (const float*)d_in[6];
    float* out = (float*)d_out;

    const int attn_smem = (NPAD * QS + NPAD * VS) * 4 + NPAD * 4;  // 93632 B
    cudaFuncSetAttribute(attn_flash,
                         cudaFuncAttributeMaxDynamicSharedMemorySize, attn_smem);

    dim3 g1(M_ROWS / 64, QKV_N / 128);    // (1323, 6)
    qkv_gemm_tc<<<g1, 128>>>(x, Wq, bq, Wkv, bkv);

    attn_flash<<<NWIN * HEADS, 256, attn_smem>>>(bias);

    dim3 g2(M_ROWS / 64, D_MODEL / 128);  // (1323, 2)
    out_gemm_tc<<<g2, 128>>>(Wout, out);
}

// round 11
// speedup vs baseline: 3.1317x; 1.0035x over previous
#include <cuda_runtime.h>

// ---------------------------------------------------------------------------
// Problem constants
// ---------------------------------------------------------------------------
#define NTOK    294
#define NPAD    304            // padded tokens (19 * 16)
#define NT16    19
#define NWIN    288
#define D_MODEL 256
#define HEADS   8
#define DH      32
#define M_ROWS  (NWIN * NTOK)  // 84672
#define QKV_N   768

// smem strides (floats), conflict-free for the tf32 fragment access patterns
#define QS   36   // K rows (32 cols): banks 4g+t bijective
#define VS   40   // V rows (32 cols): banks 8t+g bijective
#define BS2  136  // GEMM B tile rows (128 cols): banks 8t+g bijective

// ---------------------------------------------------------------------------
// Scratch
// ---------------------------------------------------------------------------
__device__ float g_q   [(size_t)NWIN * HEADS * NTOK * DH];
__device__ float g_k   [(size_t)NWIN * HEADS * NTOK * DH];
__device__ float g_v   [(size_t)NWIN * HEADS * NTOK * DH];
__device__ float g_ctx [(size_t)M_ROWS * D_MODEL];
__device__ float g_wqkv[256 * 768];   // [k][n], tf32 bits
__device__ float g_wout[256 * 256];   // [k][n], tf32 bits

__device__ __forceinline__ int x_offset(int r) {
    int w  = r / NTOK;  int t   = r - w * NTOK;
    int bb = w / 144;   int rem = w - bb * 144;
    int gx = rem / 12;  int gy  = rem - gx * 12;
    int l  = t / 49;    int t2  = t - l * 49;
    int w1 = t2 / 7;    int w2  = t2 - w1 * 7;
    return (((((bb * 6 + l) * 12 + gx) * 12 + gy) * 7 + w1) * 7 + w2) * D_MODEL;
}

__device__ __forceinline__ unsigned f2tf(float f) {
    unsigned u;
    asm("cvt.rna.tf32.f32 %0, %1;" : "=r"(u) : "f"(f));
    return u;
}
__device__ __forceinline__ unsigned fbits(float f) { return __float_as_uint(f); }

__device__ __forceinline__ void mma_tf32(float c[4], const unsigned a[4], const unsigned b[2]) {
    asm volatile(
        "mma.sync.aligned.m16n8k8.row.col.f32.tf32.tf32.f32 "
        "{%0,%1,%2,%3}, {%4,%5,%6,%7}, {%8,%9}, {%0,%1,%2,%3};"
        : "+f"(c[0]), "+f"(c[1]), "+f"(c[2]), "+f"(c[3])
        : "r"(a[0]), "r"(a[1]), "r"(a[2]), "r"(a[3]), "r"(b[0]), "r"(b[1]));
}

// ===========================================================================
// Kernel 0: one-time weight conversion to tf32 ([k][n] layouts).
// ===========================================================================
__global__ __launch_bounds__(256) void conv_w(
    const float* __restrict__ Wq, const float* __restrict__ Wkv,
    const float* __restrict__ Wout)
{
    int idx = blockIdx.x * 256 + threadIdx.x;
    if (idx < 256 * 768) {
        int k = idx / 768, n = idx - k * 768;
        float v = (n < 256) ? Wq[k * 256 + n] : Wkv[k * 512 + (n - 256)];
        g_wqkv[idx] = __uint_as_float(f2tf(v));
    }
    if (idx < 256 * 256) {
        g_wout[idx] = __uint_as_float(f2tf(Wout[idx]));
    }
}

// ===========================================================================
// Kernel 1: QKV projection. CTA 64x128, 4 warps of 32x64, BK=32,
// double-buffered smem (one barrier per k-iter), B pre-converted.
// ===========================================================================
__global__ __launch_bounds__(128) void qkv_gemm_tc(
    const float* __restrict__ x,
    const float* __restrict__ bq, const float* __restrict__ bkv)
{
    __shared__ float As[2][64 * QS];
    __shared__ float Bs[2][32 * BS2];
    __shared__ int   rowbase[64];

    const int tid  = threadIdx.x;
    const int lane = tid & 31, wid = tid >> 5;
    const int wm = wid & 1, wn = wid >> 1;
    const int g = lane >> 2, t = lane & 3;
    const int r0 = blockIdx.x * 64;
    const int c0 = blockIdx.y * 128;

    if (tid < 64) rowbase[tid] = x_offset(r0 + tid);
    __syncthreads();

    int arow[4], astore[4], boff[8], bstore[8];
#pragma unroll
    for (int i = 0; i < 4; i++) {
        int idx = tid + i * 128;
        int ar = idx >> 3, aq = idx & 7;
        arow[i]   = rowbase[ar] + aq * 4;
        astore[i] = ar * QS + aq * 4;
    }
#pragma unroll
    for (int i = 0; i < 8; i++) {
        int idx = tid + i * 128;
        int bk = idx >> 5, bc = idx & 31;
        boff[i]   = bk * QKV_N + c0 + bc * 4;
        bstore[i] = bk * BS2 + bc * 4;
    }

    float acc[2][8][4];
#pragma unroll
    for (int m = 0; m < 2; m++)
#pragma unroll
        for (int n = 0; n < 8; n++)
#pragma unroll
            for (int e = 0; e < 4; e++) acc[m][n][e] = 0.f;

    float4 av[4], bv[8];
#pragma unroll
    for (int i = 0; i < 4; i++) av[i] = *(const float4*)(x + arow[i]);
#pragma unroll
    for (int i = 0; i < 8; i++) bv[i] = *(const float4*)(g_wqkv + boff[i]);
#pragma unroll
    for (int i = 0; i < 4; i++) {
        float* ap = As[0] + astore[i];
        ap[0] = __uint_as_float(f2tf(av[i].x));
        ap[1] = __uint_as_float(f2tf(av[i].y));
        ap[2] = __uint_as_float(f2tf(av[i].z));
        ap[3] = __uint_as_float(f2tf(av[i].w));
    }
#pragma unroll
    for (int i = 0; i < 8; i++) *(float4*)(Bs[0] + bstore[i]) = bv[i];
    __syncthreads();

    for (int it = 0; it < 8; it++) {
        const int cur = it & 1;
        if (it < 7) {
            const int k0 = (it + 1) * 32;
#pragma unroll
            for (int i = 0; i < 4; i++)
                av[i] = *(const float4*)(x + arow[i] + k0);
#pragma unroll
            for (int i = 0; i < 8; i++)
                bv[i] = *(const float4*)(g_wqkv + boff[i] + k0 * QKV_N);
        }
#pragma unroll
        for (int kk = 0; kk < 4; kk++) {
            unsigned afr[2][4];
#pragma unroll
            for (int mt = 0; mt < 2; mt++) {
                int mr = wm * 32 + mt * 16;
                afr[mt][0] = fbits(As[cur][(mr + g)     * QS + kk * 8 + t]);
                afr[mt][1] = fbits(As[cur][(mr + g + 8) * QS + kk * 8 + t]);
                afr[mt][2] = fbits(As[cur][(mr + g)     * QS + kk * 8 + t + 4]);
                afr[mt][3] = fbits(As[cur][(mr + g + 8) * QS + kk * 8 + t + 4]);
            }
#pragma unroll
            for (int nt = 0; nt < 8; nt++) {
                int nc = wn * 64 + nt * 8;
                unsigned bfr[2];
                bfr[0] = fbits(Bs[cur][(kk * 8 + t)     * BS2 + nc + g]);
                bfr[1] = fbits(Bs[cur][(kk * 8 + t + 4) * BS2 + nc + g]);
                mma_tf32(acc[0][nt], afr[0], bfr);
                mma_tf32(acc[1][nt], afr[1], bfr);
            }
        }
        if (it < 7) {
            const int nxt = cur ^ 1;
#pragma unroll
            for (int i = 0; i < 4; i++) {
                float* ap = As[nxt] + astore[i];
                ap[0] = __uint_as_float(f2tf(av[i].x));
                ap[1] = __uint_as_float(f2tf(av[i].y));
                ap[2] = __uint_as_float(f2tf(av[i].z));
                ap[3] = __uint_as_float(f2tf(av[i].w));
            }
#pragma unroll
            for (int i = 0; i < 8; i++) *(float4*)(Bs[nxt] + bstore[i]) = bv[i];
            __syncthreads();
        }
    }

    const float scale = 0.17677669529663687f;
#pragma unroll
    for (int mt = 0; mt < 2; mt++) {
#pragma unroll
        for (int e = 0; e < 2; e++) {
            int r = r0 + wm * 32 + mt * 16 + g + e * 8;
            int w = r / NTOK;  int tok = r - w * NTOK;
#pragma unroll
            for (int nt = 0; nt < 8; nt++) {
#pragma unroll
                for (int c2 = 0; c2 < 2; c2++) {
                    int nc = c0 + wn * 64 + nt * 8 + 2 * t + c2;
                    float va = acc[mt][nt][e * 2 + c2];
                    if (nc < D_MODEL) {
                        int h = nc >> 5, c = nc & 31;
                        g_q[(((size_t)w * HEADS + h) * NTOK + tok) * DH + c] =
                            __uint_as_float(f2tf((va + __ldg(bq + nc)) * scale));
                    } else {
                        int kc = nc - D_MODEL;
                        float val = __uint_as_float(f2tf(va + __ldg(bkv + kc)));
                        if (kc < D_MODEL) {
                            int h = kc >> 5, c = kc & 31;
                            g_k[(((size_t)w * HEADS + h) * NTOK + tok) * DH + c] = val;
                        } else {
                            int vc = kc - D_MODEL;
                            int h = vc >> 5, c = vc & 31;
                            g_v[(((size_t)w * HEADS + h) * NTOK + tok) * DH + c] = val;
                        }
                    }
                }
            }
        }
    }
}

// ===========================================================================
// Kernel 2: register-resident flash attention, TWO 16-row query tiles per
// warp sharing every K/V fragment load. One CTA per (window, head).
// ===========================================================================
__global__ __launch_bounds__(256, 2) void attn_flash(const float* __restrict__ bias_table)
{
    extern __shared__ float sm[];
    float* Ks = sm;                       // NPAD x 36
    float* Vs = sm + NPAD * QS;           // NPAD x 40
    int*   bJ = (int*)(Vs + NPAD * VS);   // NPAD

    const int wh = blockIdx.x;
    const int w  = wh >> 3, h = wh & 7;
    const int tid = threadIdx.x;
    const int lane = tid & 31, wid = tid >> 5;
    const int g = lane >> 2, t = lane & 3;

    const float* kg = g_k + (size_t)wh * NTOK * DH;
    const float* vg = g_v + (size_t)wh * NTOK * DH;
    for (int idx = tid; idx < NTOK * 8; idx += 256) {
        int row = idx >> 3, q4 = (idx & 7) * 4;
        *(float4*)(Ks + row * QS + q4) = *(const float4*)(kg + row * DH + q4);
        *(float4*)(Vs + row * VS + q4) = *(const float4*)(vg + row * DH + q4);
    }
    for (int idx = tid; idx < (NPAD - NTOK) * 8; idx += 256) {
        int row = NTOK + (idx >> 3), q4 = (idx & 7) * 4;
        float4 z = make_float4(0.f, 0.f, 0.f, 0.f);
        *(float4*)(Ks + row * QS + q4) = z;
        *(float4*)(Vs + row * VS + q4) = z;
    }
    for (int j = tid; j < NPAD; j += 256) {
        int jj = min(j, NTOK - 1);
        int l = jj / 49, r2 = jj - l * 49, a = r2 / 7, b = r2 - a * 7;
        bJ[j] = l * 169 + a * 13 + b;
    }
    __syncthreads();

    const float* qg = g_q + (size_t)wh * NTOK * DH;

    // 10 tile-pairs over 8 warps: pair p covers tiles (2p, min(2p+1,18))
    for (int p = wid; p < 10; p += 8) {
        const int mtA = 2 * p;
        const int mtB = min(2 * p + 1, NT16 - 1);

        const int rA0 = mtA * 16 + g, rA1 = rA0 + 8;
        const int rB0 = mtB * 16 + g, rB1 = rB0 + 8;
        const int cA0 = min(rA0, NTOK - 1), cA1 = min(rA1, NTOK - 1);
        const int cB0 = min(rB0, NTOK - 1), cB1 = min(rB1, NTOK - 1);

        int CiA0, CiA1, CiB0, CiB1;
        {
            int l, r2, a, b;
            l = cA0 / 49; r2 = cA0 - l * 49; a = r2 / 7; b = r2 - a * 7;
            CiA0 = (l + 5) * 169 + (a + 6) * 13 + (b + 6);
            l = cA1 / 49; r2 = cA1 - l * 49; a = r2 / 7; b = r2 - a * 7;
            CiA1 = (l + 5) * 169 + (a + 6) * 13 + (b + 6);
            l = cB0 / 49; r2 = cB0 - l * 49; a = r2 / 7; b = r2 - a * 7;
            CiB0 = (l + 5) * 169 + (a + 6) * 13 + (b + 6);
            l = cB1 / 49; r2 = cB1 - l * 49; a = r2 / 7; b = r2 - a * 7;
            CiB1 = (l + 5) * 169 + (a + 6) * 13 + (b + 6);
        }

        unsigned qaA[4][4], qaB[4][4];
#pragma unroll
        for (int kk = 0; kk < 4; kk++) {
            qaA[kk][0] = fbits(__ldg(qg + cA0 * DH + kk * 8 + t));
            qaA[kk][1] = fbits(__ldg(qg + cA1 * DH + kk * 8 + t));
            qaA[kk][2] = fbits(__ldg(qg + cA0 * DH + kk * 8 + t + 4));
            qaA[kk][3] = fbits(__ldg(qg + cA1 * DH + kk * 8 + t + 4));
            qaB[kk][0] = fbits(__ldg(qg + cB0 * DH + kk * 8 + t));
            qaB[kk][1] = fbits(__ldg(qg + cB1 * DH + kk * 8 + t));
            qaB[kk][2] = fbits(__ldg(qg + cB0 * DH + kk * 8 + t + 4));
            qaB[kk][3] = fbits(__ldg(qg + cB1 * DH + kk * 8 + t + 4));
        }

        float OA[4][4], OB[4][4];
#pragma unroll
        for (int ot = 0; ot < 4; ot++)
#pragma unroll
            for (int e = 0; e < 4; e++) { OA[ot][e] = 0.f; OB[ot][e] = 0.f; }
        float sA0 = 0.f, sA1 = 0.f, sB0 = 0.f, sB1 = 0.f;

        const int src1 = (lane & 28) | (t >> 1);
        const int src2 = src1 + 2;

        for (int nt = 0; nt < 37; nt++) {
            float cA[4] = {0.f, 0.f, 0.f, 0.f};
            float cB[4] = {0.f, 0.f, 0.f, 0.f};
#pragma unroll
            for (int kk = 0; kk < 4; kk++) {
                unsigned b[2];
                b[0] = fbits(Ks[(nt * 8 + g) * QS + kk * 8 + t]);
                b[1] = fbits(Ks[(nt * 8 + g) * QS + kk * 8 + t + 4]);
                mma_tf32(cA, qaA[kk], b);
                mma_tf32(cB, qaB[kk], b);
            }

            const int j0 = nt * 8 + 2 * t, j1 = j0 + 1;
            const int bj0 = bJ[j0], bj1 = bJ[j1];
            const bool v0 = (j0 < NTOK), v1 = (j1 < NTOK);

            float pA0 = v0 ? __expf(cA[0] + __ldg(bias_table + (size_t)(CiA0 - bj0) * HEADS + h)) : 0.f;
            float pA1 = v1 ? __expf(cA[1] + __ldg(bias_table + (size_t)(CiA0 - bj1) * HEADS + h)) : 0.f;
            float pA2 = v0 ? __expf(cA[2] + __ldg(bias_table + (size_t)(CiA1 - bj0) * HEADS + h)) : 0.f;
            float pA3 = v1 ? __expf(cA[3] + __ldg(bias_table + (size_t)(CiA1 - bj1) * HEADS + h)) : 0.f;
            float pB0 = v0 ? __expf(cB[0] + __ldg(bias_table + (size_t)(CiB0 - bj0) * HEADS + h)) : 0.f;
            float pB1 = v1 ? __expf(cB[1] + __ldg(bias_table + (size_t)(CiB0 - bj1) * HEADS + h)) : 0.f;
            float pB2 = v0 ? __expf(cB[2] + __ldg(bias_table + (size_t)(CiB1 - bj0) * HEADS + h)) : 0.f;
            float pB3 = v1 ? __expf(cB[3] + __ldg(bias_table + (size_t)(CiB1 - bj1) * HEADS + h)) : 0.f;
            sA0 += pA0 + pA1;  sA1 += pA2 + pA3;
            sB0 += pB0 + pB1;  sB1 += pB2 + pB3;

            unsigned uA0 = f2tf(pA0), uA1 = f2tf(pA1), uA2 = f2tf(pA2), uA3 = f2tf(pA3);
            unsigned uB0 = f2tf(pB0), uB1 = f2tf(pB1), uB2 = f2tf(pB2), uB3 = f2tf(pB3);

            unsigned paA[4], paB[4];
            {
                unsigned a0 = __shfl_sync(0xffffffffu, uA0, src1);
                unsigned a1 = __shfl_sync(0xffffffffu, uA1, src1);
                unsigned a2 = __shfl_sync(0xffffffffu, uA2, src1);
                unsigned a3 = __shfl_sync(0xffffffffu, uA3, src1);
                unsigned b0 = __shfl_sync(0xffffffffu, uA0, src2);
                unsigned b1 = __shfl_sync(0xffffffffu, uA1, src2);
                unsigned b2 = __shfl_sync(0xffffffffu, uA2, src2);
                unsigned b3 = __shfl_sync(0xffffffffu, uA3, src2);
                paA[0] = (t & 1) ? a1 : a0;
                paA[1] = (t & 1) ? a3 : a2;
                paA[2] = (t & 1) ? b1 : b0;
                paA[3] = (t & 1) ? b3 : b2;
            }
            {
                unsigned a0 = __shfl_sync(0xffffffffu, uB0, src1);
                unsigned a1 = __shfl_sync(0xffffffffu, uB1, src1);
                unsigned a2 = __shfl_sync(0xffffffffu, uB2, src1);
                unsigned a3 = __shfl_sync(0xffffffffu, uB3, src1);
                unsigned b0 = __shfl_sync(0xffffffffu, uB0, src2);
                unsigned b1 = __shfl_sync(0xffffffffu, uB1, src2);
                unsigned b2 = __shfl_sync(0xffffffffu, uB2, src2);
                unsigned b3 = __shfl_sync(0xffffffffu, uB3, src2);
                paB[0] = (t & 1) ? a1 : a0;
                paB[1] = (t & 1) ? a3 : a2;
                paB[2] = (t & 1) ? b1 : b0;
                paB[3] = (t & 1) ? b3 : b2;
            }

#pragma unroll
            for (int ot = 0; ot < 4; ot++) {
                unsigned vb[2];
                vb[0] = fbits(Vs[(nt * 8 + t)     * VS + ot * 8 + g]);
                vb[1] = fbits(Vs[(nt * 8 + t + 4) * VS + ot * 8 + g]);
                mma_tf32(OA[ot], paA, vb);
                mma_tf32(OB[ot], paB, vb);
            }
        }

        sA0 += __shfl_xor_sync(0xffffffffu, sA0, 1);
        sA0 += __shfl_xor_sync(0xffffffffu, sA0, 2);
        sA1 += __shfl_xor_sync(0xffffffffu, sA1, 1);
        sA1 += __shfl_xor_sync(0xffffffffu, sA1, 2);
        sB0 += __shfl_xor_sync(0xffffffffu, sB0, 1);
        sB0 += __shfl_xor_sync(0xffffffffu, sB0, 2);
        sB1 += __shfl_xor_sync(0xffffffffu, sB1, 1);
        sB1 += __shfl_xor_sync(0xffffffffu, sB1, 2);
        const float iA0 = 1.f / sA0, iA1 = 1.f / sA1;
        const float iB0 = 1.f / sB0, iB1 = 1.f / sB1;

        if (rA0 < NTOK) {
            float* d = g_ctx + ((size_t)w * NTOK + rA0) * D_MODEL + h * DH;
#pragma unroll
            for (int ot = 0; ot < 4; ot++)
                *(float2*)(d + ot * 8 + 2 * t) =
                    make_float2(__uint_as_float(f2tf(OA[ot][0] * iA0)),
                                __uint_as_float(f2tf(OA[ot][1] * iA0)));
        }
        if (rA1 < NTOK) {
            float* d = g_ctx + ((size_t)w * NTOK + rA1) * D_MODEL + h * DH;
#pragma unroll
            for (int ot = 0; ot < 4; ot++)
                *(float2*)(d + ot * 8 + 2 * t) =
                    make_float2(__uint_as_float(f2tf(OA[ot][2] * iA1)),
                                __uint_as_float(f2tf(OA[ot][3] * iA1)));
        }
        if (mtB != mtA) {
            if (rB0 < NTOK) {
                float* d = g_ctx + ((size_t)w * NTOK + rB0) * D_MODEL + h * DH;
#pragma unroll
                for (int ot = 0; ot < 4; ot++)
                    *(float2*)(d + ot * 8 + 2 * t) =
                        make_float2(__uint_as_float(f2tf(OB[ot][0] * iB0)),
                                    __uint_as_float(f2tf(OB[ot][1] * iB0)));
            }
            if (rB1 < NTOK) {
                float* d = g_ctx + ((size_t)w * NTOK + rB1) * D_MODEL + h * DH;
#pragma unroll
                for (int ot = 0; ot < 4; ot++)
                    *(float2*)(d + ot * 8 + 2 * t) =
                        make_float2(__uint_as_float(f2tf(OB[ot][2] * iB1)),
                                    __uint_as_float(f2tf(OB[ot][3] * iB1)));
            }
        }
    }
}

// ===========================================================================
// Kernel 3: output projection. Double-buffered, zero cvts in the hot loop.
// ===========================================================================
__global__ __launch_bounds__(128) void out_gemm_tc(float* __restrict__ out)
{
    __shared__ float As[2][64 * QS];
    __shared__ float Bs[2][32 * BS2];
    __shared__ int   rowbase[64];

    const int tid  = threadIdx.x;
    const int lane = tid & 31, wid = tid >> 5;
    const int wm = wid & 1, wn = wid >> 1;
    const int g = lane >> 2, t = lane & 3;
    const int r0 = blockIdx.x * 64;
    const int c0 = blockIdx.y * 128;

    if (tid < 64) rowbase[tid] = x_offset(r0 + tid);
    __syncthreads();

    int aoff[4], astore[4], boff[8], bstore[8];
#pragma unroll
    for (int i = 0; i < 4; i++) {
        int idx = tid + i * 128;
        int ar = idx >> 3, aq = idx & 7;
        aoff[i]   = (r0 + ar) * D_MODEL + aq * 4;
        astore[i] = ar * QS + aq * 4;
    }
#pragma unroll
    for (int i = 0; i < 8; i++) {
        int idx = tid + i * 128;
        int bk = idx >> 5, bc = idx & 31;
        boff[i]   = bk * D_MODEL + c0 + bc * 4;
        bstore[i] = bk * BS2 + bc * 4;
    }

    float acc[2][8][4];
#pragma unroll
    for (int m = 0; m < 2; m++)
#pragma unroll
        for (int n = 0; n < 8; n++)
#pragma unroll
            for (int e = 0; e < 4; e++) acc[m][n][e] = 0.f;

    float4 av[4], bv[8];
#pragma unroll
    for (int i = 0; i < 4; i++) av[i] = *(const float4*)(g_ctx + aoff[i]);
#pragma unroll
    for (int i = 0; i < 8; i++) bv[i] = *(const float4*)(g_wout + boff[i]);
#pragma unroll
    for (int i = 0; i < 4; i++) *(float4*)(As[0] + astore[i]) = av[i];
#pragma unroll
    for (int i = 0; i < 8; i++) *(float4*)(Bs[0] + bstore[i]) = bv[i];
    __syncthreads();

    for (int it = 0; it < 8; it++) {
        const int cur = it & 1;
        if (it < 7) {
            const int k0 = (it + 1) * 32;
#pragma unroll
            for (int i = 0; i < 4; i++)
                av[i] = *(const float4*)(g_ctx + aoff[i] + k0);
#pragma unroll
            for (int i = 0; i < 8; i++)
                bv[i] = *(const float4*)(g_wout + boff[i] + k0 * D_MODEL);
        }
#pragma unroll
        for (int kk = 0; kk < 4; kk++) {
            unsigned afr[2][4];
#pragma unroll
            for (int mt = 0; mt < 2; mt++) {
                int mr = wm * 32 + mt * 16;
                afr[mt][0] = fbits(As[cur][(mr + g)     * QS + kk * 8 + t]);
                afr[mt][1] = fbits(As[cur][(mr + g + 8) * QS + kk * 8 + t]);
                afr[mt][2] = fbits(As[cur][(mr + g)     * QS + kk * 8 + t + 4]);
                afr[mt][3] = fbits(As[cur][(mr + g + 8) * QS + kk * 8 + t + 4]);
            }
#pragma unroll
            for (int nt = 0; nt < 8; nt++) {
                int nc = wn * 64 + nt * 8;
                unsigned bfr[2];
                bfr[0] = fbits(Bs[cur][(kk * 8 + t)     * BS2 + nc + g]);
                bfr[1] = fbits(Bs[cur][(kk * 8 + t + 4) * BS2 + nc + g]);
                mma_tf32(acc[0][nt], afr[0], bfr);
                mma_tf32(acc[1][nt], afr[1], bfr);
            }
        }
        if (it < 7) {
            const int nxt = cur ^ 1;
#pragma unroll
            for (int i = 0; i < 4; i++) *(float4*)(As[nxt] + astore[i]) = av[i];
#pragma unroll
            for (int i = 0; i < 8; i++) *(float4*)(Bs[nxt] + bstore[i]) = bv[i];
            __syncthreads();
        }
    }

#pragma unroll
    for (int mt = 0; mt < 2; mt++) {
#pragma unroll
        for (int e = 0; e < 2; e++) {
            int rl = wm * 32 + mt * 16 + g + e * 8;
            int xb = rowbase[rl];
#pragma unroll
            for (int nt = 0; nt < 8; nt++) {
                int cc = c0 + wn * 64 + nt * 8 + 2 * t;
                *(float2*)(out + xb + cc) =
                    make_float2(acc[mt][nt][e * 2 + 0], acc[mt][nt][e * 2 + 1]);
            }
        }
    }
}

// ---------------------------------------------------------------------------
// Launch
// ---------------------------------------------------------------------------
extern "C" void kernel_launch(void* const* d_in, const int* in_sizes, int n_in,
                              void* d_out, int out_size)
{
    const float* x    = (const float*)d_in[0];
    const float* Wq   = (const float*)d_in[1];
    const float* bq   = (const float*)d_in[2];
    const float* Wkv  = (const float*)d_in[3];
    const float* bkv  = (const float*)d_in[4];
    const float* Wout = (const float*)d_in[5];
    const float* bias = (const float*)d_in[6];
    float* out = (float*)d_out;

    const int attn_smem = (NPAD * QS + NPAD * VS) * 4 + NPAD * 4;  // 93632 B
    cudaFuncSetAttribute(attn_flash,
                         cudaFuncAttributeMaxDynamicSharedMemorySize, attn_smem);

    conv_w<<<768, 256>>>(Wq, Wkv, Wout);

    dim3 g1(M_ROWS / 64, QKV_N / 128);    // (1323, 6)
    qkv_gemm_tc<<<g1, 128>>>(x, bq, bkv);

    attn_flash<<<NWIN * HEADS, 256, attn_smem>>>(bias);

    dim3 g2(M_ROWS / 64, D_MODEL / 128);  // (1323, 2)
    out_gemm_tc<<<g2, 128>>>(out);
}

// round 12
// speedup vs baseline: 3.3146x; 1.0584x over previous
#include <cuda_runtime.h>

// ---------------------------------------------------------------------------
// Problem constants
// ---------------------------------------------------------------------------
#define NTOK    294
#define NPAD    304            // padded tokens (19 * 16)
#define NT16    19
#define NWIN    288
#define D_MODEL 256
#define HEADS   8
#define DH      32
#define M_ROWS  (NWIN * NTOK)  // 84672
#define QKV_N   768

// smem strides (floats), conflict-free for the tf32 fragment access patterns
#define QS   36   // K rows (32 cols): banks 4g+t bijective
#define VS   40   // V rows (32 cols): banks 8t+g bijective
#define BS2  136  // GEMM B tile rows (128 cols): banks 8t+g bijective

// ---------------------------------------------------------------------------
// Scratch
// ---------------------------------------------------------------------------
__device__ float g_q   [(size_t)NWIN * HEADS * NTOK * DH];
__device__ float g_k   [(size_t)NWIN * HEADS * NTOK * DH];
__device__ float g_v   [(size_t)NWIN * HEADS * NTOK * DH];
__device__ float g_ctx [(size_t)M_ROWS * D_MODEL];
__device__ float g_wqkv[256 * 768];   // [k][n], tf32 bits
__device__ float g_wout[256 * 256];   // [k][n], tf32 bits

__device__ __forceinline__ int x_offset(int r) {
    int w  = r / NTOK;  int t   = r - w * NTOK;
    int bb = w / 144;   int rem = w - bb * 144;
    int gx = rem / 12;  int gy  = rem - gx * 12;
    int l  = t / 49;    int t2  = t - l * 49;
    int w1 = t2 / 7;    int w2  = t2 - w1 * 7;
    return (((((bb * 6 + l) * 12 + gx) * 12 + gy) * 7 + w1) * 7 + w2) * D_MODEL;
}

__device__ __forceinline__ unsigned f2tf(float f) {
    unsigned u;
    asm("cvt.rna.tf32.f32 %0, %1;" : "=r"(u) : "f"(f));
    return u;
}
__device__ __forceinline__ unsigned fbits(float f) { return __float_as_uint(f); }

__device__ __forceinline__ void mma_tf32(float c[4], const unsigned a[4], const unsigned b[2]) {
    asm volatile(
        "mma.sync.aligned.m16n8k8.row.col.f32.tf32.tf32.f32 "
        "{%0,%1,%2,%3}, {%4,%5,%6,%7}, {%8,%9}, {%0,%1,%2,%3};"
        : "+f"(c[0]), "+f"(c[1]), "+f"(c[2]), "+f"(c[3])
        : "r"(a[0]), "r"(a[1]), "r"(a[2]), "r"(a[3]), "r"(b[0]), "r"(b[1]));
}

// ===========================================================================
// Kernel 0: one-time weight conversion to tf32 ([k][n] layouts).
// ===========================================================================
__global__ __launch_bounds__(256) void conv_w(
    const float* __restrict__ Wq, const float* __restrict__ Wkv,
    const float* __restrict__ Wout)
{
    int idx = blockIdx.x * 256 + threadIdx.x;
    if (idx < 256 * 768) {
        int k = idx / 768, n = idx - k * 768;
        float v = (n < 256) ? Wq[k * 256 + n] : Wkv[k * 512 + (n - 256)];
        g_wqkv[idx] = __uint_as_float(f2tf(v));
    }
    if (idx < 256 * 256) {
        g_wout[idx] = __uint_as_float(f2tf(Wout[idx]));
    }
}

// ===========================================================================
// Kernel 1: QKV projection. CTA 64x128, 4 warps of 32x64, BK=32,
// double-buffered. Grid = (cols, rows): col-block is the FAST dimension so
// concurrently-resident CTAs share x row tiles in L2 (x read ~once).
// ===========================================================================
__global__ __launch_bounds__(128) void qkv_gemm_tc(
    const float* __restrict__ x,
    const float* __restrict__ bq, const float* __restrict__ bkv)
{
    __shared__ float As[2][64 * QS];
    __shared__ float Bs[2][32 * BS2];
    __shared__ int   rowbase[64];

    const int tid  = threadIdx.x;
    const int lane = tid & 31, wid = tid >> 5;
    const int wm = wid & 1, wn = wid >> 1;
    const int g = lane >> 2, t = lane & 3;
    const int r0 = blockIdx.y * 64;      // row block (slow dim)
    const int c0 = blockIdx.x * 128;     // col block (fast dim)

    if (tid < 64) rowbase[tid] = x_offset(r0 + tid);
    __syncthreads();

    int arow[4], astore[4], boff[8], bstore[8];
#pragma unroll
    for (int i = 0; i < 4; i++) {
        int idx = tid + i * 128;
        int ar = idx >> 3, aq = idx & 7;
        arow[i]   = rowbase[ar] + aq * 4;
        astore[i] = ar * QS + aq * 4;
    }
#pragma unroll
    for (int i = 0; i < 8; i++) {
        int idx = tid + i * 128;
        int bk = idx >> 5, bc = idx & 31;
        boff[i]   = bk * QKV_N + c0 + bc * 4;
        bstore[i] = bk * BS2 + bc * 4;
    }

    float acc[2][8][4];
#pragma unroll
    for (int m = 0; m < 2; m++)
#pragma unroll
        for (int n = 0; n < 8; n++)
#pragma unroll
            for (int e = 0; e < 4; e++) acc[m][n][e] = 0.f;

    float4 av[4], bv[8];
#pragma unroll
    for (int i = 0; i < 4; i++) av[i] = *(const float4*)(x + arow[i]);
#pragma unroll
    for (int i = 0; i < 8; i++) bv[i] = *(const float4*)(g_wqkv + boff[i]);
#pragma unroll
    for (int i = 0; i < 4; i++) {
        float* ap = As[0] + astore[i];
        ap[0] = __uint_as_float(f2tf(av[i].x));
        ap[1] = __uint_as_float(f2tf(av[i].y));
        ap[2] = __uint_as_float(f2tf(av[i].z));
        ap[3] = __uint_as_float(f2tf(av[i].w));
    }
#pragma unroll
    for (int i = 0; i < 8; i++) *(float4*)(Bs[0] + bstore[i]) = bv[i];
    __syncthreads();

    for (int it = 0; it < 8; it++) {
        const int cur = it & 1;
        if (it < 7) {
            const int k0 = (it + 1) * 32;
#pragma unroll
            for (int i = 0; i < 4; i++)
                av[i] = *(const float4*)(x + arow[i] + k0);
#pragma unroll
            for (int i = 0; i < 8; i++)
                bv[i] = *(const float4*)(g_wqkv + boff[i] + k0 * QKV_N);
        }
#pragma unroll
        for (int kk = 0; kk < 4; kk++) {
            unsigned afr[2][4];
#pragma unroll
            for (int mt = 0; mt < 2; mt++) {
                int mr = wm * 32 + mt * 16;
                afr[mt][0] = fbits(As[cur][(mr + g)     * QS + kk * 8 + t]);
                afr[mt][1] = fbits(As[cur][(mr + g + 8) * QS + kk * 8 + t]);
                afr[mt][2] = fbits(As[cur][(mr + g)     * QS + kk * 8 + t + 4]);
                afr[mt][3] = fbits(As[cur][(mr + g + 8) * QS + kk * 8 + t + 4]);
            }
#pragma unroll
            for (int nt = 0; nt < 8; nt++) {
                int nc = wn * 64 + nt * 8;
                unsigned bfr[2];
                bfr[0] = fbits(Bs[cur][(kk * 8 + t)     * BS2 + nc + g]);
                bfr[1] = fbits(Bs[cur][(kk * 8 + t + 4) * BS2 + nc + g]);
                mma_tf32(acc[0][nt], afr[0], bfr);
                mma_tf32(acc[1][nt], afr[1], bfr);
            }
        }
        if (it < 7) {
            const int nxt = cur ^ 1;
#pragma unroll
            for (int i = 0; i < 4; i++) {
                float* ap = As[nxt] + astore[i];
                ap[0] = __uint_as_float(f2tf(av[i].x));
                ap[1] = __uint_as_float(f2tf(av[i].y));
                ap[2] = __uint_as_float(f2tf(av[i].z));
                ap[3] = __uint_as_float(f2tf(av[i].w));
            }
#pragma unroll
            for (int i = 0; i < 8; i++) *(float4*)(Bs[nxt] + bstore[i]) = bv[i];
            __syncthreads();
        }
    }

    const float scale = 0.17677669529663687f;
#pragma unroll
    for (int mt = 0; mt < 2; mt++) {
#pragma unroll
        for (int e = 0; e < 2; e++) {
            int r = r0 + wm * 32 + mt * 16 + g + e * 8;
            int w = r / NTOK;  int tok = r - w * NTOK;
#pragma unroll
            for (int nt = 0; nt < 8; nt++) {
                int nc = c0 + wn * 64 + nt * 8 + 2 * t;     // even; pair {nc, nc+1}
                float va0 = acc[mt][nt][e * 2 + 0];
                float va1 = acc[mt][nt][e * 2 + 1];
                if (nc < D_MODEL) {
                    int h = nc >> 5, c = nc & 31;
                    float2 v2 = make_float2(
                        __uint_as_float(f2tf((va0 + __ldg(bq + nc))     * scale)),
                        __uint_as_float(f2tf((va1 + __ldg(bq + nc + 1)) * scale)));
                    *(float2*)(g_q + (((size_t)w * HEADS + h) * NTOK + tok) * DH + c) = v2;
                } else {
                    int kc = nc - D_MODEL;
                    float2 v2 = make_float2(
                        __uint_as_float(f2tf(va0 + __ldg(bkv + kc))),
                        __uint_as_float(f2tf(va1 + __ldg(bkv + kc + 1))));
                    if (kc < D_MODEL) {
                        int h = kc >> 5, c = kc & 31;
                        *(float2*)(g_k + (((size_t)w * HEADS + h) * NTOK + tok) * DH + c) = v2;
                    } else {
                        int vc = kc - D_MODEL;
                        int h = vc >> 5, c = vc & 31;
                        *(float2*)(g_v + (((size_t)w * HEADS + h) * NTOK + tok) * DH + c) = v2;
                    }
                }
            }
        }
    }
}

// ===========================================================================
// Kernel 2: register-resident flash attention, TWO 16-row query tiles per
// warp sharing every K/V fragment load. S-mma chains split 2-way for ILP.
// ===========================================================================
__global__ __launch_bounds__(256, 2) void attn_flash(const float* __restrict__ bias_table)
{
    extern __shared__ float sm[];
    float* Ks = sm;                       // NPAD x 36
    float* Vs = sm + NPAD * QS;           // NPAD x 40
    int*   bJ = (int*)(Vs + NPAD * VS);   // NPAD

    const int wh = blockIdx.x;
    const int w  = wh >> 3, h = wh & 7;
    const int tid = threadIdx.x;
    const int lane = tid & 31, wid = tid >> 5;
    const int g = lane >> 2, t = lane & 3;

    const float* kg = g_k + (size_t)wh * NTOK * DH;
    const float* vg = g_v + (size_t)wh * NTOK * DH;
    for (int idx = tid; idx < NTOK * 8; idx += 256) {
        int row = idx >> 3, q4 = (idx & 7) * 4;
        *(float4*)(Ks + row * QS + q4) = *(const float4*)(kg + row * DH + q4);
        *(float4*)(Vs + row * VS + q4) = *(const float4*)(vg + row * DH + q4);
    }
    for (int idx = tid; idx < (NPAD - NTOK) * 8; idx += 256) {
        int row = NTOK + (idx >> 3), q4 = (idx & 7) * 4;
        float4 z = make_float4(0.f, 0.f, 0.f, 0.f);
        *(float4*)(Ks + row * QS + q4) = z;
        *(float4*)(Vs + row * VS + q4) = z;
    }
    for (int j = tid; j < NPAD; j += 256) {
        int jj = min(j, NTOK - 1);
        int l = jj / 49, r2 = jj - l * 49, a = r2 / 7, b = r2 - a * 7;
        bJ[j] = l * 169 + a * 13 + b;
    }
    __syncthreads();

    const float* qg = g_q + (size_t)wh * NTOK * DH;

    // 10 tile-pairs over 8 warps: pair p covers tiles (2p, min(2p+1,18))
    for (int p = wid; p < 10; p += 8) {
        const int mtA = 2 * p;
        const int mtB = min(2 * p + 1, NT16 - 1);

        const int rA0 = mtA * 16 + g, rA1 = rA0 + 8;
        const int rB0 = mtB * 16 + g, rB1 = rB0 + 8;
        const int cA0 = min(rA0, NTOK - 1), cA1 = min(rA1, NTOK - 1);
        const int cB0 = min(rB0, NTOK - 1), cB1 = min(rB1, NTOK - 1);

        int CiA0, CiA1, CiB0, CiB1;
        {
            int l, r2, a, b;
            l = cA0 / 49; r2 = cA0 - l * 49; a = r2 / 7; b = r2 - a * 7;
            CiA0 = (l + 5) * 169 + (a + 6) * 13 + (b + 6);
            l = cA1 / 49; r2 = cA1 - l * 49; a = r2 / 7; b = r2 - a * 7;
            CiA1 = (l + 5) * 169 + (a + 6) * 13 + (b + 6);
            l = cB0 / 49; r2 = cB0 - l * 49; a = r2 / 7; b = r2 - a * 7;
            CiB0 = (l + 5) * 169 + (a + 6) * 13 + (b + 6);
            l = cB1 / 49; r2 = cB1 - l * 49; a = r2 / 7; b = r2 - a * 7;
            CiB1 = (l + 5) * 169 + (a + 6) * 13 + (b + 6);
        }

        unsigned qaA[4][4], qaB[4][4];
#pragma unroll
        for (int kk = 0; kk < 4; kk++) {
            qaA[kk][0] = fbits(__ldg(qg + cA0 * DH + kk * 8 + t));
            qaA[kk][1] = fbits(__ldg(qg + cA1 * DH + kk * 8 + t));
            qaA[kk][2] = fbits(__ldg(qg + cA0 * DH + kk * 8 + t + 4));
            qaA[kk][3] = fbits(__ldg(qg + cA1 * DH + kk * 8 + t + 4));
            qaB[kk][0] = fbits(__ldg(qg + cB0 * DH + kk * 8 + t));
            qaB[kk][1] = fbits(__ldg(qg + cB1 * DH + kk * 8 + t));
            qaB[kk][2] = fbits(__ldg(qg + cB0 * DH + kk * 8 + t + 4));
            qaB[kk][3] = fbits(__ldg(qg + cB1 * DH + kk * 8 + t + 4));
        }

        float OA[4][4], OB[4][4];
#pragma unroll
        for (int ot = 0; ot < 4; ot++)
#pragma unroll
            for (int e = 0; e < 4; e++) { OA[ot][e] = 0.f; OB[ot][e] = 0.f; }
        float sA0 = 0.f, sA1 = 0.f, sB0 = 0.f, sB1 = 0.f;

        const int src1 = (lane & 28) | (t >> 1);
        const int src2 = src1 + 2;

        for (int nt = 0; nt < 37; nt++) {
            // Two independent 2-chains per tile (ILP), combined at the end.
            float cAx[4] = {0.f, 0.f, 0.f, 0.f}, cAy[4] = {0.f, 0.f, 0.f, 0.f};
            float cBx[4] = {0.f, 0.f, 0.f, 0.f}, cBy[4] = {0.f, 0.f, 0.f, 0.f};
#pragma unroll
            for (int kk = 0; kk < 2; kk++) {
                unsigned b[2];
                b[0] = fbits(Ks[(nt * 8 + g) * QS + kk * 8 + t]);
                b[1] = fbits(Ks[(nt * 8 + g) * QS + kk * 8 + t + 4]);
                mma_tf32(cAx, qaA[kk], b);
                mma_tf32(cBx, qaB[kk], b);
            }
#pragma unroll
            for (int kk = 2; kk < 4; kk++) {
                unsigned b[2];
                b[0] = fbits(Ks[(nt * 8 + g) * QS + kk * 8 + t]);
                b[1] = fbits(Ks[(nt * 8 + g) * QS + kk * 8 + t + 4]);
                mma_tf32(cAy, qaA[kk], b);
                mma_tf32(cBy, qaB[kk], b);
            }
            float cA[4], cB[4];
#pragma unroll
            for (int e = 0; e < 4; e++) { cA[e] = cAx[e] + cAy[e]; cB[e] = cBx[e] + cBy[e]; }

            const int j0 = nt * 8 + 2 * t, j1 = j0 + 1;
            const int bj0 = bJ[j0], bj1 = bJ[j1];
            const bool v0 = (j0 < NTOK), v1 = (j1 < NTOK);

            float pA0 = v0 ? __expf(cA[0] + __ldg(bias_table + (size_t)(CiA0 - bj0) * HEADS + h)) : 0.f;
            float pA1 = v1 ? __expf(cA[1] + __ldg(bias_table + (size_t)(CiA0 - bj1) * HEADS + h)) : 0.f;
            float pA2 = v0 ? __expf(cA[2] + __ldg(bias_table + (size_t)(CiA1 - bj0) * HEADS + h)) : 0.f;
            float pA3 = v1 ? __expf(cA[3] + __ldg(bias_table + (size_t)(CiA1 - bj1) * HEADS + h)) : 0.f;
            float pB0 = v0 ? __expf(cB[0] + __ldg(bias_table + (size_t)(CiB0 - bj0) * HEADS + h)) : 0.f;
            float pB1 = v1 ? __expf(cB[1] + __ldg(bias_table + (size_t)(CiB0 - bj1) * HEADS + h)) : 0.f;
            float pB2 = v0 ? __expf(cB[2] + __ldg(bias_table + (size_t)(CiB1 - bj0) * HEADS + h)) : 0.f;
            float pB3 = v1 ? __expf(cB[3] + __ldg(bias_table + (size_t)(CiB1 - bj1) * HEADS + h)) : 0.f;
            sA0 += pA0 + pA1;  sA1 += pA2 + pA3;
            sB0 += pB0 + pB1;  sB1 += pB2 + pB3;

            unsigned uA0 = f2tf(pA0), uA1 = f2tf(pA1), uA2 = f2tf(pA2), uA3 = f2tf(pA3);
            unsigned uB0 = f2tf(pB0), uB1 = f2tf(pB1), uB2 = f2tf(pB2), uB3 = f2tf(pB3);

            unsigned paA[4], paB[4];
            {
                unsigned a0 = __shfl_sync(0xffffffffu, uA0, src1);
                unsigned a1 = __shfl_sync(0xffffffffu, uA1, src1);
                unsigned a2 = __shfl_sync(0xffffffffu, uA2, src1);
                unsigned a3 = __shfl_sync(0xffffffffu, uA3, src1);
                unsigned b0 = __shfl_sync(0xffffffffu, uA0, src2);
                unsigned b1 = __shfl_sync(0xffffffffu, uA1, src2);
                unsigned b2 = __shfl_sync(0xffffffffu, uA2, src2);
                unsigned b3 = __shfl_sync(0xffffffffu, uA3, src2);
                paA[0] = (t & 1) ? a1 : a0;
                paA[1] = (t & 1) ? a3 : a2;
                paA[2] = (t & 1) ? b1 : b0;
                paA[3] = (t & 1) ? b3 : b2;
            }
            {
                unsigned a0 = __shfl_sync(0xffffffffu, uB0, src1);
                unsigned a1 = __shfl_sync(0xffffffffu, uB1, src1);
                unsigned a2 = __shfl_sync(0xffffffffu, uB2, src1);
                unsigned a3 = __shfl_sync(0xffffffffu, uB3, src1);
                unsigned b0 = __shfl_sync(0xffffffffu, uB0, src2);
                unsigned b1 = __shfl_sync(0xffffffffu, uB1, src2);
                unsigned b2 = __shfl_sync(0xffffffffu, uB2, src2);
                unsigned b3 = __shfl_sync(0xffffffffu, uB3, src2);
                paB[0] = (t & 1) ? a1 : a0;
                paB[1] = (t & 1) ? a3 : a2;
                paB[2] = (t & 1) ? b1 : b0;
                paB[3] = (t & 1) ? b3 : b2;
            }

#pragma unroll
            for (int ot = 0; ot < 4; ot++) {
                unsigned vb[2];
                vb[0] = fbits(Vs[(nt * 8 + t)     * VS + ot * 8 + g]);
                vb[1] = fbits(Vs[(nt * 8 + t + 4) * VS + ot * 8 + g]);
                mma_tf32(OA[ot], paA, vb);
                mma_tf32(OB[ot], paB, vb);
            }
        }

        sA0 += __shfl_xor_sync(0xffffffffu, sA0, 1);
        sA0 += __shfl_xor_sync(0xffffffffu, sA0, 2);
        sA1 += __shfl_xor_sync(0xffffffffu, sA1, 1);
        sA1 += __shfl_xor_sync(0xffffffffu, sA1, 2);
        sB0 += __shfl_xor_sync(0xffffffffu, sB0, 1);
        sB0 += __shfl_xor_sync(0xffffffffu, sB0, 2);
        sB1 += __shfl_xor_sync(0xffffffffu, sB1, 1);
        sB1 += __shfl_xor_sync(0xffffffffu, sB1, 2);
        const float iA0 = 1.f / sA0, iA1 = 1.f / sA1;
        const float iB0 = 1.f / sB0, iB1 = 1.f / sB1;

        if (rA0 < NTOK) {
            float* d = g_ctx + ((size_t)w * NTOK + rA0) * D_MODEL + h * DH;
#pragma unroll
            for (int ot = 0; ot < 4; ot++)
                *(float2*)(d + ot * 8 + 2 * t) =
                    make_float2(__uint_as_float(f2tf(OA[ot][0] * iA0)),
                                __uint_as_float(f2tf(OA[ot][1] * iA0)));
        }
        if (rA1 < NTOK) {
            float* d = g_ctx + ((size_t)w * NTOK + rA1) * D_MODEL + h * DH;
#pragma unroll
            for (int ot = 0; ot < 4; ot++)
                *(float2*)(d + ot * 8 + 2 * t) =
                    make_float2(__uint_as_float(f2tf(OA[ot][2] * iA1)),
                                __uint_as_float(f2tf(OA[ot][3] * iA1)));
        }
        if (mtB != mtA) {
            if (rB0 < NTOK) {
                float* d = g_ctx + ((size_t)w * NTOK + rB0) * D_MODEL + h * DH;
#pragma unroll
                for (int ot = 0; ot < 4; ot++)
                    *(float2*)(d + ot * 8 + 2 * t) =
                        make_float2(__uint_as_float(f2tf(OB[ot][0] * iB0)),
                                    __uint_as_float(f2tf(OB[ot][1] * iB0)));
            }
            if (rB1 < NTOK) {
                float* d = g_ctx + ((size_t)w * NTOK + rB1) * D_MODEL + h * DH;
#pragma unroll
                for (int ot = 0; ot < 4; ot++)
                    *(float2*)(d + ot * 8 + 2 * t) =
                        make_float2(__uint_as_float(f2tf(OB[ot][2] * iB1)),
                                    __uint_as_float(f2tf(OB[ot][3] * iB1)));
            }
        }
    }
}

// ===========================================================================
// Kernel 3: output projection. Double-buffered; grid = (cols, rows) so g_ctx
// rows are L2-shared across the 2 column blocks.
// ===========================================================================
__global__ __launch_bounds__(128) void out_gemm_tc(float* __restrict__ out)
{
    __shared__ float As[2][64 * QS];
    __shared__ float Bs[2][32 * BS2];
    __shared__ int   rowbase[64];

    const int tid  = threadIdx.x;
    const int lane = tid & 31, wid = tid >> 5;
    const int wm = wid & 1, wn = wid >> 1;
    const int g = lane >> 2, t = lane & 3;
    const int r0 = blockIdx.y * 64;      // row block (slow dim)
    const int c0 = blockIdx.x * 128;     // col block (fast dim)

    if (tid < 64) rowbase[tid] = x_offset(r0 + tid);
    __syncthreads();

    int aoff[4], astore[4], boff[8], bstore[8];
#pragma unroll
    for (int i = 0; i < 4; i++) {
        int idx = tid + i * 128;
        int ar = idx >> 3, aq = idx & 7;
        aoff[i]   = (r0 + ar) * D_MODEL + aq * 4;
        astore[i] = ar * QS + aq * 4;
    }
#pragma unroll
    for (int i = 0; i < 8; i++) {
        int idx = tid + i * 128;
        int bk = idx >> 5, bc = idx & 31;
        boff[i]   = bk * D_MODEL + c0 + bc * 4;
        bstore[i] = bk * BS2 + bc * 4;
    }

    float acc[2][8][4];
#pragma unroll
    for (int m = 0; m < 2; m++)
#pragma unroll
        for (int n = 0; n < 8; n++)
#pragma unroll
            for (int e = 0; e < 4; e++) acc[m][n][e] = 0.f;

    float4 av[4], bv[8];
#pragma unroll
    for (int i = 0; i < 4; i++) av[i] = *(const float4*)(g_ctx + aoff[i]);
#pragma unroll
    for (int i = 0; i < 8; i++) bv[i] = *(const float4*)(g_wout + boff[i]);
#pragma unroll
    for (int i = 0; i < 4; i++) *(float4*)(As[0] + astore[i]) = av[i];
#pragma unroll
    for (int i = 0; i < 8; i++) *(float4*)(Bs[0] + bstore[i]) = bv[i];
    __syncthreads();

    for (int it = 0; it < 8; it++) {
        const int cur = it & 1;
        if (it < 7) {
            const int k0 = (it + 1) * 32;
#pragma unroll
            for (int i = 0; i < 4; i++)
                av[i] = *(const float4*)(g_ctx + aoff[i] + k0);
#pragma unroll
            for (int i = 0; i < 8; i++)
                bv[i] = *(const float4*)(g_wout + boff[i] + k0 * D_MODEL);
        }
#pragma unroll
        for (int kk = 0; kk < 4; kk++) {
            unsigned afr[2][4];
#pragma unroll
            for (int mt = 0; mt < 2; mt++) {
                int mr = wm * 32 + mt * 16;
                afr[mt][0] = fbits(As[cur][(mr + g)     * QS + kk * 8 + t]);
                afr[mt][1] = fbits(As[cur][(mr + g + 8) * QS + kk * 8 + t]);
                afr[mt][2] = fbits(As[cur][(mr + g)     * QS + kk * 8 + t + 4]);
                afr[mt][3] = fbits(As[cur][(mr + g + 8) * QS + kk * 8 + t + 4]);
            }
#pragma unroll
            for (int nt = 0; nt < 8; nt++) {
                int nc = wn * 64 + nt * 8;
                unsigned bfr[2];
                bfr[0] = fbits(Bs[cur][(kk * 8 + t)     * BS2 + nc + g]);
                bfr[1] = fbits(Bs[cur][(kk * 8 + t + 4) * BS2 + nc + g]);
                mma_tf32(acc[0][nt], afr[0], bfr);
                mma_tf32(acc[1][nt], afr[1], bfr);
            }
        }
        if (it < 7) {
            const int nxt = cur ^ 1;
#pragma unroll
            for (int i = 0; i < 4; i++) *(float4*)(As[nxt] + astore[i]) = av[i];
#pragma unroll
            for (int i = 0; i < 8; i++) *(float4*)(Bs[nxt] + bstore[i]) = bv[i];
            __syncthreads();
        }
    }

#pragma unroll
    for (int mt = 0; mt < 2; mt++) {
#pragma unroll
        for (int e = 0; e < 2; e++) {
            int rl = wm * 32 + mt * 16 + g + e * 8;
            int xb = rowbase[rl];
#pragma unroll
            for (int nt = 0; nt < 8; nt++) {
                int cc = c0 + wn * 64 + nt * 8 + 2 * t;
                *(float2*)(out + xb + cc) =
                    make_float2(acc[mt][nt][e * 2 + 0], acc[mt][nt][e * 2 + 1]);
            }
        }
    }
}

// ---------------------------------------------------------------------------
// Launch
// ---------------------------------------------------------------------------
extern "C" void kernel_launch(void* const* d_in, const int* in_sizes, int n_in,
                              void* d_out, int out_size)
{
    const float* x    = (const float*)d_in[0];
    const float* Wq   = (const float*)d_in[1];
    const float* bq   = (const float*)d_in[2];
    const float* Wkv  = (const float*)d_in[3];
    const float* bkv  = (const float*)d_in[4];
    const float* Wout = (const float*)d_in[5];
    const float* bias = (const float*)d_in[6];
    float* out = (float*)d_out;

    const int attn_smem = (NPAD * QS + NPAD * VS) * 4 + NPAD * 4;  // 93632 B
    cudaFuncSetAttribute(attn_flash,
                         cudaFuncAttributeMaxDynamicSharedMemorySize, attn_smem);

    conv_w<<<768, 256>>>(Wq, Wkv, Wout);

    dim3 g1(QKV_N / 128, M_ROWS / 64);    // (6, 1323) — cols fast
    qkv_gemm_tc<<<g1, 128>>>(x, bq, bkv);

    attn_flash<<<NWIN * HEADS, 256, attn_smem>>>(bias);

    dim3 g2(D_MODEL / 128, M_ROWS / 64);  // (2, 1323) — cols fast
    out_gemm_tc<<<g2, 128>>>(out);
}